// round 9
// baseline (speedup 1.0000x reference)
#include <cuda_runtime.h>
#include <cuda_bf16.h>
#include <cstddef>
#include <cstdint>

// Problem constants
#define Bq  2
#define Sq  2048
#define Hq  2048
#define NHq 32
#define HDq 64

// Scratch buffers
__device__ float    g_Q[Bq * Sq * Hq];
__device__ float    g_K[Bq * Sq * Hq];
__device__ float    g_V[Bq * Sq * Hq];
__device__ uint32_t g_Xhi[Bq * Sq * Hq];
__device__ uint32_t g_Xlo[Bq * Sq * Hq];
__device__ uint32_t g_Ahi[Bq * Sq * Hq];
__device__ uint32_t g_Alo[Bq * Sq * Hq];
__device__ uint32_t g_Whq[Hq * Hq];
__device__ uint32_t g_Whk[Hq * Hq];
__device__ uint32_t g_Whv[Hq * Hq];
__device__ uint32_t g_Who[Hq * Hq];

// ---------------------------------------------------------------------------
// Helpers
// ---------------------------------------------------------------------------
__device__ __forceinline__ uint32_t smem_to_u32(const void* smem_ptr) {
    uint32_t addr;
    asm("{ .reg .u64 tmp; cvta.to.shared.u64 tmp, %1; cvt.u32.u64 %0, tmp; }"
        : "=r"(addr) : "l"(smem_ptr));
    return addr;
}

__device__ __forceinline__ void tf32_split(float x, uint32_t& hi, uint32_t& lo) {
    asm("cvt.rna.tf32.f32 %0, %1;" : "=r"(hi) : "f"(x));
    float l = x - __uint_as_float(hi);
    asm("cvt.rna.tf32.f32 %0, %1;" : "=r"(lo) : "f"(l));
}

__device__ __forceinline__ uint32_t tf32_rna(float x) {
    uint32_t r;
    asm("cvt.rna.tf32.f32 %0, %1;" : "=r"(r) : "f"(x));
    return r;
}

__device__ __forceinline__ void mma_tf32(float c[4], const uint32_t a[4],
                                         const uint32_t b[2]) {
    asm volatile(
        "mma.sync.aligned.m16n8k8.row.col.f32.tf32.tf32.f32 "
        "{%0,%1,%2,%3}, {%4,%5,%6,%7}, {%8,%9}, {%0,%1,%2,%3};\n"
        : "+f"(c[0]), "+f"(c[1]), "+f"(c[2]), "+f"(c[3])
        : "r"(a[0]), "r"(a[1]), "r"(a[2]), "r"(a[3]), "r"(b[0]), "r"(b[1]));
}

#define CP_ASYNC16(dst_u32, src_ptr) \
    asm volatile("cp.async.cg.shared.global [%0], [%1], 16;" \
                 :: "r"(dst_u32), "l"(src_ptr) : "memory")
#define CP_COMMIT() asm volatile("cp.async.commit_group;" ::: "memory")
#define CP_WAIT1()  asm volatile("cp.async.wait_group 1;" ::: "memory")
#define CP_WAIT0()  asm volatile("cp.async.wait_group 0;" ::: "memory")

// ---------------------------------------------------------------------------
// Pre-pass: split X into tf32 hi/lo planes; round W to a single tf32 plane.
// ---------------------------------------------------------------------------
__global__ void split_plane_kernel(const float4* __restrict__ src,
                                   uint4* __restrict__ hi,
                                   uint4* __restrict__ lo, int n4) {
    int i = blockIdx.x * blockDim.x + threadIdx.x;
    if (i >= n4) return;
    float4 v = src[i];
    uint4 h, l;
    tf32_split(v.x, h.x, l.x);
    tf32_split(v.y, h.y, l.y);
    tf32_split(v.z, h.z, l.z);
    tf32_split(v.w, h.w, l.w);
    hi[i] = h;
    lo[i] = l;
}

__global__ void round_w_kernel(const float4* __restrict__ w0,
                               const float4* __restrict__ w1,
                               const float4* __restrict__ w2,
                               const float4* __restrict__ w3,
                               uint4* __restrict__ d0, uint4* __restrict__ d1,
                               uint4* __restrict__ d2, uint4* __restrict__ d3,
                               int n4) {
    int i = blockIdx.x * blockDim.x + threadIdx.x;
    if (i >= n4) return;
    const float4* s = (blockIdx.y == 0) ? w0 : (blockIdx.y == 1) ? w1
                      : (blockIdx.y == 2) ? w2 : w3;
    uint4* d = (blockIdx.y == 0) ? d0 : (blockIdx.y == 1) ? d1
               : (blockIdx.y == 2) ? d2 : d3;
    float4 v = s[i];
    uint4 r;
    r.x = tf32_rna(v.x); r.y = tf32_rna(v.y);
    r.z = tf32_rna(v.z); r.w = tf32_rna(v.w);
    d[i] = r;
}

// ---------------------------------------------------------------------------
// Plane GEMM (NT): C[m][n] = sum_k (Ahi+Alo)[m][k] * Bh[n][k], all tf32.
// Block tile 128x128, K-chunk 32, 256 threads, warp tile 64x32.
// cp.async 2-stage pipeline; smem [row][36]-padded (conflict-free LDS).
// ---------------------------------------------------------------------------
#define TPAD 36
#define PLANE_WORDS (128 * TPAD)        // 4608
#define STAGE_WORDS (3 * PLANE_WORDS)   // 13824
#define GEMM_SMEM (2 * STAGE_WORDS * 4) // 110,592 B

__device__ __forceinline__ void gemm_pl_core(uint32_t* sm,
        const uint32_t* __restrict__ Ahi_g,
        const uint32_t* __restrict__ Alo_g,
        const uint32_t* __restrict__ Bh_g,
        float* __restrict__ C, int M, int N, int K, int m0, int n0) {
    const int tid  = threadIdx.x;
    const int lane = tid & 31;
    const int wid  = tid >> 5;
    const int wm   = (wid & 1) * 64;
    const int wn   = (wid >> 1) * 32;
    const int g    = lane >> 2;
    const int tig  = lane & 3;

    const int lrow = tid >> 1;   // 0..127
    const int lkb  = tid & 1;    // 0..1

    const uint32_t sm_base = smem_to_u32(sm);

    const uint32_t* srcA = Ahi_g + (size_t)(m0 + lrow) * K;
    const uint32_t* srcL = Alo_g + (size_t)(m0 + lrow) * K;
    const uint32_t* srcB = Bh_g  + (size_t)(n0 + lrow) * K;

    float acc[4][4][4];
#pragma unroll
    for (int i = 0; i < 4; ++i)
#pragma unroll
        for (int j = 0; j < 4; ++j)
#pragma unroll
            for (int r = 0; r < 4; ++r) acc[i][j][r] = 0.0f;

    // Issue one stage's copies (12 x 16B per thread)
    auto issue = [&](int stage, int ch) {
        uint32_t dbase = sm_base +
            (uint32_t)(stage * STAGE_WORDS + lrow * TPAD) * 4u;
        const int kofs = ch * 32;
#pragma unroll
        for (int i = 0; i < 4; ++i) {
            int kg = lkb + 2 * i;
            CP_ASYNC16(dbase + kg * 16, srcA + kofs + kg * 4);
            CP_ASYNC16(dbase + PLANE_WORDS * 4 + kg * 16, srcL + kofs + kg * 4);
            CP_ASYNC16(dbase + 2 * PLANE_WORDS * 4 + kg * 16, srcB + kofs + kg * 4);
        }
        CP_COMMIT();
    };

    const int NCH = K >> 5;
    issue(0, 0);

    for (int ch = 0; ch < NCH; ++ch) {
        const int s = ch & 1;
        if (ch + 1 < NCH) {
            issue(s ^ 1, ch + 1);
            CP_WAIT1();
        } else {
            CP_WAIT0();
        }
        __syncthreads();

        const uint32_t* sA = sm + s * STAGE_WORDS;
        const uint32_t* sL = sA + PLANE_WORDS;
        const uint32_t* sB = sL + PLANE_WORDS;

#pragma unroll
        for (int ks = 0; ks < 4; ++ks) {
            const int ka = ks * 8 + tig;
            const int kb = ka + 4;

            uint32_t ah[4][4], al[4][4];
#pragma unroll
            for (int ma = 0; ma < 4; ++ma) {
                int r0 = (wm + ma * 16 + g) * TPAD;
                int r1 = r0 + 8 * TPAD;
                ah[ma][0] = sA[r0 + ka];
                ah[ma][1] = sA[r1 + ka];
                ah[ma][2] = sA[r0 + kb];
                ah[ma][3] = sA[r1 + kb];
                al[ma][0] = sL[r0 + ka];
                al[ma][1] = sL[r1 + ka];
                al[ma][2] = sL[r0 + kb];
                al[ma][3] = sL[r1 + kb];
            }
            uint32_t bh[4][2];
#pragma unroll
            for (int na = 0; na < 4; ++na) {
                int c = (wn + na * 8 + g) * TPAD;
                bh[na][0] = sB[c + ka];
                bh[na][1] = sB[c + kb];
            }
#pragma unroll
            for (int ma = 0; ma < 4; ++ma)
#pragma unroll
                for (int na = 0; na < 4; ++na) {
                    mma_tf32(acc[ma][na], ah[ma], bh[na]);
                    mma_tf32(acc[ma][na], al[ma], bh[na]);
                }
        }
        __syncthreads();
    }

#pragma unroll
    for (int ma = 0; ma < 4; ++ma) {
        int r0 = m0 + wm + ma * 16 + g;
#pragma unroll
        for (int na = 0; na < 4; ++na) {
            int c = n0 + wn + na * 8 + 2 * tig;
            *(float2*)&C[(size_t)r0 * N + c] =
                make_float2(acc[ma][na][0], acc[ma][na][1]);
            *(float2*)&C[(size_t)(r0 + 8) * N + c] =
                make_float2(acc[ma][na][2], acc[ma][na][3]);
        }
    }
}

__global__ __launch_bounds__(256)
void gemm_pl_nt(const uint32_t* __restrict__ Ahi,
                const uint32_t* __restrict__ Alo,
                const uint32_t* __restrict__ Bh,
                float* __restrict__ C, int M, int N, int K) {
    extern __shared__ uint32_t smg[];
    gemm_pl_core(smg, Ahi, Alo, Bh, C, M, N, K,
                 blockIdx.y * 128, blockIdx.x * 128);
}

// Fused QKV: blockIdx.x in [0,48): selects W plane and output buffer.
__global__ __launch_bounds__(256)
void gemm_pl_qkv(const uint32_t* __restrict__ Xhi,
                 const uint32_t* __restrict__ Xlo,
                 const uint32_t* __restrict__ Whq,
                 const uint32_t* __restrict__ Whk,
                 const uint32_t* __restrict__ Whv,
                 float* __restrict__ Qo, float* __restrict__ Ko,
                 float* __restrict__ Vo) {
    extern __shared__ uint32_t smg[];
    const int which = blockIdx.x >> 4;
    const uint32_t* W = (which == 0) ? Whq : (which == 1) ? Whk : Whv;
    float* C = (which == 0) ? Qo : (which == 1) ? Ko : Vo;
    gemm_pl_core(smg, Xhi, Xlo, W, C, Bq * Sq, Hq, Hq,
                 blockIdx.y * 128, (blockIdx.x & 15) * 128);
}

// ---------------------------------------------------------------------------
// RoPE (in-place) on Q and K. Q also folded with 1/sqrt(HD) = 0.125.
// ---------------------------------------------------------------------------
__global__ void rope_kernel(float* __restrict__ Q, float* __restrict__ K,
                            const float* __restrict__ cs,
                            const float* __restrict__ sn) {
    const int PAIRS = Bq * Sq * NHq * (HDq / 2);
    int idx = blockIdx.x * blockDim.x + threadIdx.x;
    if (idx >= 2 * PAIRS) return;
    bool isQ = idx < PAIRS;
    int p = isQ ? idx : idx - PAIRS;

    int d = p & 31;
    int h = (p >> 5) & 31;
    int s = (p >> 10) & 2047;
    int b = p >> 21;

    size_t base = ((size_t)(b * Sq + s) * Hq) + (size_t)h * HDq + d;
    float c1 = cs[s * HDq + d],      s1 = sn[s * HDq + d];
    float c2 = cs[s * HDq + d + 32], s2 = sn[s * HDq + d + 32];

    float* T = isQ ? Q : K;
    float scale = isQ ? 0.125f : 1.0f;
    float x1 = T[base];
    float x2 = T[base + 32];
    T[base]      = (x1 * c1 - x2 * s1) * scale;
    T[base + 32] = (x2 * c2 + x1 * s2) * scale;
}

// ---------------------------------------------------------------------------
// Flash attention on tensor cores, 2-mma tf32 split (R7-validated).
// Epilogue writes the output directly as tf32 hi/lo planes for the O-proj.
// ---------------------------------------------------------------------------
__global__ __launch_bounds__(256, 2)
void attn_mma(const float* __restrict__ Q, const float* __restrict__ K,
              const float* __restrict__ V, const float* __restrict__ mask,
              uint32_t* __restrict__ Ohi, uint32_t* __restrict__ Olo) {
    extern __shared__ uint32_t sma[];
    float*    Qs  = (float*)sma;          // 8192 floats
    uint32_t* Ks  = sma + 8192;           // 4096 (tf32 bits)
    uint32_t* Vs  = sma + 12288;          // 4096 (tf32 bits)
    float*    Ps  = (float*)(sma + 16384);// 8192 floats
    float*    msk = (float*)(sma + 24576);// 64

    const int tid  = threadIdx.x;
    const int lane = tid & 31;
    const int wid  = tid >> 5;
    const int g    = lane >> 2;
    const int tig  = lane & 3;
    const int R    = wid * 16 + g;
    const int R8   = R + 8;
    const int sw   = g << 2;

    const int b  = blockIdx.z;
    const int h  = blockIdx.y;
    const int q0 = blockIdx.x * 128;
    const size_t ho = (size_t)h * HDq;

    const float* Qb = Q + ((size_t)(b * Sq + q0) * Hq) + ho;
#pragma unroll
    for (int it = 0; it < 8; ++it) {
        int f = tid + it * 256;
        int r = f >> 4, d0 = (f & 15) << 2;
        float4 v = *(const float4*)(Qb + (size_t)r * Hq + d0);
        *(float4*)&Qs[r * 64 + (d0 ^ ((r & 7) << 2))] = v;
    }

    float o[8][4];
#pragma unroll
    for (int na = 0; na < 8; ++na)
#pragma unroll
        for (int e = 0; e < 4; ++e) o[na][e] = 0.0f;
    float mrow[2] = {-1e30f, -1e30f};
    float lrow[2] = {0.0f, 0.0f};

    for (int t = 0; t < Sq / 64; ++t) {
        const int c0 = t * 64;
        const float* Kb = K + ((size_t)(b * Sq + c0) * Hq) + ho;
        const float* Vb = V + ((size_t)(b * Sq + c0) * Hq) + ho;
#pragma unroll
        for (int it = 0; it < 4; ++it) {
            int f = tid + it * 256;
            int r = f >> 4, d0 = (f & 15) << 2;
            float4 kv = *(const float4*)(Kb + (size_t)r * Hq + d0);
            uint4 kq;
            kq.x = tf32_rna(kv.x); kq.y = tf32_rna(kv.y);
            kq.z = tf32_rna(kv.z); kq.w = tf32_rna(kv.w);
            *(uint4*)&Ks[r * 64 + (d0 ^ ((r & 7) << 2))] = kq;
            float4 vv = *(const float4*)(Vb + (size_t)r * Hq + d0);
            uint4 vq;
            vq.x = tf32_rna(vv.x); vq.y = tf32_rna(vv.y);
            vq.z = tf32_rna(vv.z); vq.w = tf32_rna(vv.w);
            *(uint4*)&Vs[r * 64 + (d0 ^ ((r & 7) << 3))] = vq;
        }
        if (tid < 16)
            *(float4*)&msk[tid * 4] =
                *(const float4*)(mask + (size_t)b * Sq + c0 + tid * 4);
        __syncthreads();

        // ---- S = Q @ K^T ----
        float s[8][4];
#pragma unroll
        for (int na = 0; na < 8; ++na)
#pragma unroll
            for (int e = 0; e < 4; ++e) s[na][e] = 0.0f;

#pragma unroll
        for (int ks = 0; ks < 8; ++ks) {
            const int ka = ks * 8 + tig;
            const int kb2 = ka + 4;
            uint32_t ah[4], al[4];
            tf32_split(Qs[R * 64 + (ka ^ sw)],  ah[0], al[0]);
            tf32_split(Qs[R8 * 64 + (ka ^ sw)], ah[1], al[1]);
            tf32_split(Qs[R * 64 + (kb2 ^ sw)], ah[2], al[2]);
            tf32_split(Qs[R8 * 64 + (kb2 ^ sw)], ah[3], al[3]);
#pragma unroll
            for (int na = 0; na < 8; ++na) {
                int c = na * 8 + g;
                uint32_t bh[2];
                bh[0] = Ks[c * 64 + (ka ^ sw)];
                bh[1] = Ks[c * 64 + (kb2 ^ sw)];
                mma_tf32(s[na], ah, bh);
                mma_tf32(s[na], al, bh);
            }
        }

        // ---- mask + online softmax ----
#pragma unroll
        for (int na = 0; na < 8; ++na) {
            float m0 = msk[na * 8 + 2 * tig];
            float m1 = msk[na * 8 + 2 * tig + 1];
            s[na][0] += m0; s[na][1] += m1;
            s[na][2] += m0; s[na][3] += m1;
        }

        float mx0 = -1e30f, mx1 = -1e30f;
#pragma unroll
        for (int na = 0; na < 8; ++na) {
            mx0 = fmaxf(mx0, fmaxf(s[na][0], s[na][1]));
            mx1 = fmaxf(mx1, fmaxf(s[na][2], s[na][3]));
        }
        mx0 = fmaxf(mx0, __shfl_xor_sync(0xffffffffu, mx0, 1));
        mx0 = fmaxf(mx0, __shfl_xor_sync(0xffffffffu, mx0, 2));
        mx1 = fmaxf(mx1, __shfl_xor_sync(0xffffffffu, mx1, 1));
        mx1 = fmaxf(mx1, __shfl_xor_sync(0xffffffffu, mx1, 2));

        float mn0 = fmaxf(mrow[0], mx0);
        float mn1 = fmaxf(mrow[1], mx1);
        float fac0 = __expf(mrow[0] - mn0);
        float fac1 = __expf(mrow[1] - mn1);
        mrow[0] = mn0; mrow[1] = mn1;

        float sum0 = 0.0f, sum1 = 0.0f;
#pragma unroll
        for (int na = 0; na < 8; ++na) {
            s[na][0] = __expf(s[na][0] - mn0); sum0 += s[na][0];
            s[na][1] = __expf(s[na][1] - mn0); sum0 += s[na][1];
            s[na][2] = __expf(s[na][2] - mn1); sum1 += s[na][2];
            s[na][3] = __expf(s[na][3] - mn1); sum1 += s[na][3];
        }
        sum0 += __shfl_xor_sync(0xffffffffu, sum0, 1);
        sum0 += __shfl_xor_sync(0xffffffffu, sum0, 2);
        sum1 += __shfl_xor_sync(0xffffffffu, sum1, 1);
        sum1 += __shfl_xor_sync(0xffffffffu, sum1, 2);
        lrow[0] = lrow[0] * fac0 + sum0;
        lrow[1] = lrow[1] * fac1 + sum1;

#pragma unroll
        for (int na = 0; na < 8; ++na) {
            o[na][0] *= fac0; o[na][1] *= fac0;
            o[na][2] *= fac1; o[na][3] *= fac1;
        }

        // ---- store P (warp-private rows) ----
#pragma unroll
        for (int na = 0; na < 8; ++na) {
            int col = na * 8 + 2 * tig;
            *(float2*)&Ps[R * 64 + (col ^ sw)] = make_float2(s[na][0], s[na][1]);
            *(float2*)&Ps[R8 * 64 + (col ^ sw)] = make_float2(s[na][2], s[na][3]);
        }
        __syncwarp();

        // ---- O += P @ V ----
#pragma unroll
        for (int ks = 0; ks < 8; ++ks) {
            const int kva = ks * 8 + tig;
            const int kvb = kva + 4;
            uint32_t ph[4], pl[4];
            tf32_split(Ps[R * 64 + (kva ^ sw)],  ph[0], pl[0]);
            tf32_split(Ps[R8 * 64 + (kva ^ sw)], ph[1], pl[1]);
            tf32_split(Ps[R * 64 + (kvb ^ sw)],  ph[2], pl[2]);
            tf32_split(Ps[R8 * 64 + (kvb ^ sw)], ph[3], pl[3]);
            const int swa = tig << 3;
            const int swb = (tig + 4) << 3;
#pragma unroll
            for (int na = 0; na < 8; ++na) {
                int c = na * 8 + g;
                uint32_t vh[2];
                vh[0] = Vs[kva * 64 + (c ^ swa)];
                vh[1] = Vs[kvb * 64 + (c ^ swb)];
                mma_tf32(o[na], ph, vh);
                mma_tf32(o[na], pl, vh);
            }
        }
        __syncthreads();
    }

    // Epilogue: normalize and emit tf32 hi/lo planes
    float i0 = 1.0f / lrow[0];
    float i1 = 1.0f / lrow[1];
    const size_t obase = ((size_t)(b * Sq + q0) * Hq) + ho;
#pragma unroll
    for (int na = 0; na < 8; ++na) {
        int col = na * 8 + 2 * tig;
        float v0 = o[na][0] * i0, v1 = o[na][1] * i0;
        float v2 = o[na][2] * i1, v3 = o[na][3] * i1;
        uint2 h01, l01, h23, l23;
        tf32_split(v0, h01.x, l01.x);
        tf32_split(v1, h01.y, l01.y);
        tf32_split(v2, h23.x, l23.x);
        tf32_split(v3, h23.y, l23.y);
        *(uint2*)&Ohi[obase + (size_t)R * Hq + col]  = h01;
        *(uint2*)&Olo[obase + (size_t)R * Hq + col]  = l01;
        *(uint2*)&Ohi[obase + (size_t)R8 * Hq + col] = h23;
        *(uint2*)&Olo[obase + (size_t)R8 * Hq + col] = l23;
    }
}

// ---------------------------------------------------------------------------
// Launch
// ---------------------------------------------------------------------------
extern "C" void kernel_launch(void* const* d_in, const int* in_sizes, int n_in,
                              void* d_out, int out_size) {
    const float* X    = (const float*)d_in[0];
    const float* mask = (const float*)d_in[1];
    const float* cs   = (const float*)d_in[2];
    const float* sn   = (const float*)d_in[3];
    const float* Wq   = (const float*)d_in[4];
    const float* Wk   = (const float*)d_in[5];
    const float* Wv   = (const float*)d_in[6];
    const float* Wo   = (const float*)d_in[7];
    float* out = (float*)d_out;

    float *Qp, *Kp, *Vp;
    uint32_t *Xhi, *Xlo, *Ahi, *Alo, *Whq, *Whk, *Whv, *Who;
    cudaGetSymbolAddress((void**)&Qp, g_Q);
    cudaGetSymbolAddress((void**)&Kp, g_K);
    cudaGetSymbolAddress((void**)&Vp, g_V);
    cudaGetSymbolAddress((void**)&Xhi, g_Xhi);
    cudaGetSymbolAddress((void**)&Xlo, g_Xlo);
    cudaGetSymbolAddress((void**)&Ahi, g_Ahi);
    cudaGetSymbolAddress((void**)&Alo, g_Alo);
    cudaGetSymbolAddress((void**)&Whq, g_Whq);
    cudaGetSymbolAddress((void**)&Whk, g_Whk);
    cudaGetSymbolAddress((void**)&Whv, g_Whv);
    cudaGetSymbolAddress((void**)&Who, g_Who);

    const int M = Bq * Sq;                          // 4096
    const size_t shm_g = GEMM_SMEM;                 // 110,592
    const size_t shm_a = 24640u * sizeof(uint32_t); // 98,560

    static bool attr_set = false;
    if (!attr_set) {
        cudaFuncSetAttribute(gemm_pl_nt,
                             cudaFuncAttributeMaxDynamicSharedMemorySize,
                             (int)shm_g);
        cudaFuncSetAttribute(gemm_pl_qkv,
                             cudaFuncAttributeMaxDynamicSharedMemorySize,
                             (int)shm_g);
        cudaFuncSetAttribute(attn_mma,
                             cudaFuncAttributeMaxDynamicSharedMemorySize,
                             (int)shm_a);
        attr_set = true;
    }

    // Pre-pass: split X, round weights
    const int nx4 = Bq * Sq * Hq / 4;   // 2,097,152
    split_plane_kernel<<<nx4 / 256, 256>>>((const float4*)X,
                                           (uint4*)Xhi, (uint4*)Xlo, nx4);
    const int nw4 = Hq * Hq / 4;        // 1,048,576
    round_w_kernel<<<dim3(nw4 / 256, 4), 256>>>(
        (const float4*)Wq, (const float4*)Wk,
        (const float4*)Wv, (const float4*)Wo,
        (uint4*)Whq, (uint4*)Whk, (uint4*)Whv, (uint4*)Who, nw4);

    // QKV projection (fused, plane inputs)
    gemm_pl_qkv<<<dim3(48, M / 128), 256, shm_g>>>(Xhi, Xlo, Whq, Whk, Whv,
                                                   Qp, Kp, Vp);

    const int PAIRS = Bq * Sq * NHq * (HDq / 2);
    rope_kernel<<<(2 * PAIRS + 255) / 256, 256>>>(Qp, Kp, cs, sn);

    attn_mma<<<dim3(Sq / 128, NHq, Bq), 256, shm_a>>>(Qp, Kp, Vp, mask,
                                                      Ahi, Alo);

    gemm_pl_nt<<<dim3(Hq / 128, M / 128), 256, shm_g>>>(Ahi, Alo, Who, out,
                                                        M, Hq, Hq);
}

// round 10
// speedup vs baseline: 1.0173x; 1.0173x over previous
#include <cuda_runtime.h>
#include <cuda_bf16.h>
#include <cstddef>
#include <cstdint>

// Problem constants
#define Bq  2
#define Sq  2048
#define Hq  2048
#define NHq 32
#define HDq 64

// Scratch buffers
__device__ float    g_Q[Bq * Sq * Hq];
__device__ float    g_K[Bq * Sq * Hq];
__device__ float    g_V[Bq * Sq * Hq];
__device__ uint32_t g_Xhi[Bq * Sq * Hq];
__device__ uint32_t g_Xlo[Bq * Sq * Hq];
__device__ uint32_t g_Ahi[Bq * Sq * Hq];
__device__ uint32_t g_Alo[Bq * Sq * Hq];
__device__ uint32_t g_Whq[Hq * Hq];
__device__ uint32_t g_Whk[Hq * Hq];
__device__ uint32_t g_Whv[Hq * Hq];
__device__ uint32_t g_Who[Hq * Hq];

// ---------------------------------------------------------------------------
// Helpers
// ---------------------------------------------------------------------------
__device__ __forceinline__ uint32_t smem_to_u32(const void* smem_ptr) {
    uint32_t addr;
    asm("{ .reg .u64 tmp; cvta.to.shared.u64 tmp, %1; cvt.u32.u64 %0, tmp; }"
        : "=r"(addr) : "l"(smem_ptr));
    return addr;
}

__device__ __forceinline__ void tf32_split(float x, uint32_t& hi, uint32_t& lo) {
    asm("cvt.rna.tf32.f32 %0, %1;" : "=r"(hi) : "f"(x));
    float l = x - __uint_as_float(hi);
    asm("cvt.rna.tf32.f32 %0, %1;" : "=r"(lo) : "f"(l));
}

__device__ __forceinline__ uint32_t tf32_rna(float x) {
    uint32_t r;
    asm("cvt.rna.tf32.f32 %0, %1;" : "=r"(r) : "f"(x));
    return r;
}

__device__ __forceinline__ void mma_tf32(float c[4], const uint32_t a[4],
                                         const uint32_t b[2]) {
    asm volatile(
        "mma.sync.aligned.m16n8k8.row.col.f32.tf32.tf32.f32 "
        "{%0,%1,%2,%3}, {%4,%5,%6,%7}, {%8,%9}, {%0,%1,%2,%3};\n"
        : "+f"(c[0]), "+f"(c[1]), "+f"(c[2]), "+f"(c[3])
        : "r"(a[0]), "r"(a[1]), "r"(a[2]), "r"(a[3]), "r"(b[0]), "r"(b[1]));
}

#define CP_ASYNC16(dst_u32, src_ptr) \
    asm volatile("cp.async.cg.shared.global [%0], [%1], 16;" \
                 :: "r"(dst_u32), "l"(src_ptr) : "memory")
#define CP_COMMIT() asm volatile("cp.async.commit_group;" ::: "memory")
#define CP_WAIT1()  asm volatile("cp.async.wait_group 1;" ::: "memory")
#define CP_WAIT0()  asm volatile("cp.async.wait_group 0;" ::: "memory")

// ---------------------------------------------------------------------------
// Pre-pass: split X into tf32 hi/lo planes; round W to a single tf32 plane.
// ---------------------------------------------------------------------------
__global__ void split_plane_kernel(const float4* __restrict__ src,
                                   uint4* __restrict__ hi,
                                   uint4* __restrict__ lo, int n4) {
    int i = blockIdx.x * blockDim.x + threadIdx.x;
    if (i >= n4) return;
    float4 v = src[i];
    uint4 h, l;
    tf32_split(v.x, h.x, l.x);
    tf32_split(v.y, h.y, l.y);
    tf32_split(v.z, h.z, l.z);
    tf32_split(v.w, h.w, l.w);
    hi[i] = h;
    lo[i] = l;
}

__global__ void round_w_kernel(const float4* __restrict__ w0,
                               const float4* __restrict__ w1,
                               const float4* __restrict__ w2,
                               const float4* __restrict__ w3,
                               uint4* __restrict__ d0, uint4* __restrict__ d1,
                               uint4* __restrict__ d2, uint4* __restrict__ d3,
                               int n4) {
    int i = blockIdx.x * blockDim.x + threadIdx.x;
    if (i >= n4) return;
    const float4* s = (blockIdx.y == 0) ? w0 : (blockIdx.y == 1) ? w1
                      : (blockIdx.y == 2) ? w2 : w3;
    uint4* d = (blockIdx.y == 0) ? d0 : (blockIdx.y == 1) ? d1
               : (blockIdx.y == 2) ? d2 : d3;
    float4 v = s[i];
    uint4 r;
    r.x = tf32_rna(v.x); r.y = tf32_rna(v.y);
    r.z = tf32_rna(v.z); r.w = tf32_rna(v.w);
    d[i] = r;
}

// ---------------------------------------------------------------------------
// Plane GEMM (NT): C[m][n] = sum_k (Ahi+Alo)[m][k] * Bh[n][k], all tf32.
// Block tile 128x128, K-chunk 32, 256 threads, warp tile 64x32.
// cp.async 2-stage pipeline; smem [row][36]-padded (conflict-free LDS).
// __launch_bounds__(256, 2): cap regs at 128 so 2 CTAs co-reside per SM
// (216 KB smem < 228 KB) — cross-CTA latency hiding for mma + LDS.
// ---------------------------------------------------------------------------
#define TPAD 36
#define PLANE_WORDS (128 * TPAD)        // 4608
#define STAGE_WORDS (3 * PLANE_WORDS)   // 13824
#define GEMM_SMEM (2 * STAGE_WORDS * 4) // 110,592 B

__device__ __forceinline__ void gemm_pl_core(uint32_t* sm,
        const uint32_t* __restrict__ Ahi_g,
        const uint32_t* __restrict__ Alo_g,
        const uint32_t* __restrict__ Bh_g,
        float* __restrict__ C, int M, int N, int K, int m0, int n0) {
    const int tid  = threadIdx.x;
    const int lane = tid & 31;
    const int wid  = tid >> 5;
    const int wm   = (wid & 1) * 64;
    const int wn   = (wid >> 1) * 32;
    const int g    = lane >> 2;
    const int tig  = lane & 3;

    const int lrow = tid >> 1;   // 0..127
    const int lkb  = tid & 1;    // 0..1

    const uint32_t sm_base = smem_to_u32(sm);

    const uint32_t* srcA = Ahi_g + (size_t)(m0 + lrow) * K;
    const uint32_t* srcL = Alo_g + (size_t)(m0 + lrow) * K;
    const uint32_t* srcB = Bh_g  + (size_t)(n0 + lrow) * K;

    float acc[4][4][4];
#pragma unroll
    for (int i = 0; i < 4; ++i)
#pragma unroll
        for (int j = 0; j < 4; ++j)
#pragma unroll
            for (int r = 0; r < 4; ++r) acc[i][j][r] = 0.0f;

    // Issue one stage's copies (12 x 16B per thread)
    auto issue = [&](int stage, int ch) {
        uint32_t dbase = sm_base +
            (uint32_t)(stage * STAGE_WORDS + lrow * TPAD) * 4u;
        const int kofs = ch * 32;
#pragma unroll
        for (int i = 0; i < 4; ++i) {
            int kg = lkb + 2 * i;
            CP_ASYNC16(dbase + kg * 16, srcA + kofs + kg * 4);
            CP_ASYNC16(dbase + PLANE_WORDS * 4 + kg * 16, srcL + kofs + kg * 4);
            CP_ASYNC16(dbase + 2 * PLANE_WORDS * 4 + kg * 16, srcB + kofs + kg * 4);
        }
        CP_COMMIT();
    };

    const int NCH = K >> 5;
    issue(0, 0);

    for (int ch = 0; ch < NCH; ++ch) {
        const int s = ch & 1;
        if (ch + 1 < NCH) {
            issue(s ^ 1, ch + 1);
            CP_WAIT1();
        } else {
            CP_WAIT0();
        }
        __syncthreads();

        const uint32_t* sA = sm + s * STAGE_WORDS;
        const uint32_t* sL = sA + PLANE_WORDS;
        const uint32_t* sB = sL + PLANE_WORDS;

#pragma unroll
        for (int ks = 0; ks < 4; ++ks) {
            const int ka = ks * 8 + tig;
            const int kb = ka + 4;

            uint32_t ah[4][4], al[4][4];
#pragma unroll
            for (int ma = 0; ma < 4; ++ma) {
                int r0 = (wm + ma * 16 + g) * TPAD;
                int r1 = r0 + 8 * TPAD;
                ah[ma][0] = sA[r0 + ka];
                ah[ma][1] = sA[r1 + ka];
                ah[ma][2] = sA[r0 + kb];
                ah[ma][3] = sA[r1 + kb];
                al[ma][0] = sL[r0 + ka];
                al[ma][1] = sL[r1 + ka];
                al[ma][2] = sL[r0 + kb];
                al[ma][3] = sL[r1 + kb];
            }
            uint32_t bh[4][2];
#pragma unroll
            for (int na = 0; na < 4; ++na) {
                int c = (wn + na * 8 + g) * TPAD;
                bh[na][0] = sB[c + ka];
                bh[na][1] = sB[c + kb];
            }
#pragma unroll
            for (int ma = 0; ma < 4; ++ma)
#pragma unroll
                for (int na = 0; na < 4; ++na) {
                    mma_tf32(acc[ma][na], ah[ma], bh[na]);
                    mma_tf32(acc[ma][na], al[ma], bh[na]);
                }
        }
        __syncthreads();
    }

#pragma unroll
    for (int ma = 0; ma < 4; ++ma) {
        int r0 = m0 + wm + ma * 16 + g;
#pragma unroll
        for (int na = 0; na < 4; ++na) {
            int c = n0 + wn + na * 8 + 2 * tig;
            *(float2*)&C[(size_t)r0 * N + c] =
                make_float2(acc[ma][na][0], acc[ma][na][1]);
            *(float2*)&C[(size_t)(r0 + 8) * N + c] =
                make_float2(acc[ma][na][2], acc[ma][na][3]);
        }
    }
}

__global__ __launch_bounds__(256, 2)
void gemm_pl_nt(const uint32_t* __restrict__ Ahi,
                const uint32_t* __restrict__ Alo,
                const uint32_t* __restrict__ Bh,
                float* __restrict__ C, int M, int N, int K) {
    extern __shared__ uint32_t smg[];
    gemm_pl_core(smg, Ahi, Alo, Bh, C, M, N, K,
                 blockIdx.y * 128, blockIdx.x * 128);
}

// Fused QKV: blockIdx.x in [0,48): selects W plane and output buffer.
__global__ __launch_bounds__(256, 2)
void gemm_pl_qkv(const uint32_t* __restrict__ Xhi,
                 const uint32_t* __restrict__ Xlo,
                 const uint32_t* __restrict__ Whq,
                 const uint32_t* __restrict__ Whk,
                 const uint32_t* __restrict__ Whv,
                 float* __restrict__ Qo, float* __restrict__ Ko,
                 float* __restrict__ Vo) {
    extern __shared__ uint32_t smg[];
    const int which = blockIdx.x >> 4;
    const uint32_t* W = (which == 0) ? Whq : (which == 1) ? Whk : Whv;
    float* C = (which == 0) ? Qo : (which == 1) ? Ko : Vo;
    gemm_pl_core(smg, Xhi, Xlo, W, C, Bq * Sq, Hq, Hq,
                 blockIdx.y * 128, (blockIdx.x & 15) * 128);
}

// ---------------------------------------------------------------------------
// RoPE (in-place) on Q and K. Q also folded with 1/sqrt(HD) = 0.125.
// ---------------------------------------------------------------------------
__global__ void rope_kernel(float* __restrict__ Q, float* __restrict__ K,
                            const float* __restrict__ cs,
                            const float* __restrict__ sn) {
    const int PAIRS = Bq * Sq * NHq * (HDq / 2);
    int idx = blockIdx.x * blockDim.x + threadIdx.x;
    if (idx >= 2 * PAIRS) return;
    bool isQ = idx < PAIRS;
    int p = isQ ? idx : idx - PAIRS;

    int d = p & 31;
    int h = (p >> 5) & 31;
    int s = (p >> 10) & 2047;
    int b = p >> 21;

    size_t base = ((size_t)(b * Sq + s) * Hq) + (size_t)h * HDq + d;
    float c1 = cs[s * HDq + d],      s1 = sn[s * HDq + d];
    float c2 = cs[s * HDq + d + 32], s2 = sn[s * HDq + d + 32];

    float* T = isQ ? Q : K;
    float scale = isQ ? 0.125f : 1.0f;
    float x1 = T[base];
    float x2 = T[base + 32];
    T[base]      = (x1 * c1 - x2 * s1) * scale;
    T[base + 32] = (x2 * c2 + x1 * s2) * scale;
}

// ---------------------------------------------------------------------------
// Flash attention on tensor cores, 2-mma tf32 split (R7-validated).
// Epilogue writes the output directly as tf32 hi/lo planes for the O-proj.
// ---------------------------------------------------------------------------
__global__ __launch_bounds__(256, 2)
void attn_mma(const float* __restrict__ Q, const float* __restrict__ K,
              const float* __restrict__ V, const float* __restrict__ mask,
              uint32_t* __restrict__ Ohi, uint32_t* __restrict__ Olo) {
    extern __shared__ uint32_t sma[];
    float*    Qs  = (float*)sma;          // 8192 floats
    uint32_t* Ks  = sma + 8192;           // 4096 (tf32 bits)
    uint32_t* Vs  = sma + 12288;          // 4096 (tf32 bits)
    float*    Ps  = (float*)(sma + 16384);// 8192 floats
    float*    msk = (float*)(sma + 24576);// 64

    const int tid  = threadIdx.x;
    const int lane = tid & 31;
    const int wid  = tid >> 5;
    const int g    = lane >> 2;
    const int tig  = lane & 3;
    const int R    = wid * 16 + g;
    const int R8   = R + 8;
    const int sw   = g << 2;

    const int b  = blockIdx.z;
    const int h  = blockIdx.y;
    const int q0 = blockIdx.x * 128;
    const size_t ho = (size_t)h * HDq;

    const float* Qb = Q + ((size_t)(b * Sq + q0) * Hq) + ho;
#pragma unroll
    for (int it = 0; it < 8; ++it) {
        int f = tid + it * 256;
        int r = f >> 4, d0 = (f & 15) << 2;
        float4 v = *(const float4*)(Qb + (size_t)r * Hq + d0);
        *(float4*)&Qs[r * 64 + (d0 ^ ((r & 7) << 2))] = v;
    }

    float o[8][4];
#pragma unroll
    for (int na = 0; na < 8; ++na)
#pragma unroll
        for (int e = 0; e < 4; ++e) o[na][e] = 0.0f;
    float mrow[2] = {-1e30f, -1e30f};
    float lrow[2] = {0.0f, 0.0f};

    for (int t = 0; t < Sq / 64; ++t) {
        const int c0 = t * 64;
        const float* Kb = K + ((size_t)(b * Sq + c0) * Hq) + ho;
        const float* Vb = V + ((size_t)(b * Sq + c0) * Hq) + ho;
#pragma unroll
        for (int it = 0; it < 4; ++it) {
            int f = tid + it * 256;
            int r = f >> 4, d0 = (f & 15) << 2;
            float4 kv = *(const float4*)(Kb + (size_t)r * Hq + d0);
            uint4 kq;
            kq.x = tf32_rna(kv.x); kq.y = tf32_rna(kv.y);
            kq.z = tf32_rna(kv.z); kq.w = tf32_rna(kv.w);
            *(uint4*)&Ks[r * 64 + (d0 ^ ((r & 7) << 2))] = kq;
            float4 vv = *(const float4*)(Vb + (size_t)r * Hq + d0);
            uint4 vq;
            vq.x = tf32_rna(vv.x); vq.y = tf32_rna(vv.y);
            vq.z = tf32_rna(vv.z); vq.w = tf32_rna(vv.w);
            *(uint4*)&Vs[r * 64 + (d0 ^ ((r & 7) << 3))] = vq;
        }
        if (tid < 16)
            *(float4*)&msk[tid * 4] =
                *(const float4*)(mask + (size_t)b * Sq + c0 + tid * 4);
        __syncthreads();

        // ---- S = Q @ K^T ----
        float s[8][4];
#pragma unroll
        for (int na = 0; na < 8; ++na)
#pragma unroll
            for (int e = 0; e < 4; ++e) s[na][e] = 0.0f;

#pragma unroll
        for (int ks = 0; ks < 8; ++ks) {
            const int ka = ks * 8 + tig;
            const int kb2 = ka + 4;
            uint32_t ah[4], al[4];
            tf32_split(Qs[R * 64 + (ka ^ sw)],  ah[0], al[0]);
            tf32_split(Qs[R8 * 64 + (ka ^ sw)], ah[1], al[1]);
            tf32_split(Qs[R * 64 + (kb2 ^ sw)], ah[2], al[2]);
            tf32_split(Qs[R8 * 64 + (kb2 ^ sw)], ah[3], al[3]);
#pragma unroll
            for (int na = 0; na < 8; ++na) {
                int c = na * 8 + g;
                uint32_t bh[2];
                bh[0] = Ks[c * 64 + (ka ^ sw)];
                bh[1] = Ks[c * 64 + (kb2 ^ sw)];
                mma_tf32(s[na], ah, bh);
                mma_tf32(s[na], al, bh);
            }
        }

        // ---- mask + online softmax ----
#pragma unroll
        for (int na = 0; na < 8; ++na) {
            float m0 = msk[na * 8 + 2 * tig];
            float m1 = msk[na * 8 + 2 * tig + 1];
            s[na][0] += m0; s[na][1] += m1;
            s[na][2] += m0; s[na][3] += m1;
        }

        float mx0 = -1e30f, mx1 = -1e30f;
#pragma unroll
        for (int na = 0; na < 8; ++na) {
            mx0 = fmaxf(mx0, fmaxf(s[na][0], s[na][1]));
            mx1 = fmaxf(mx1, fmaxf(s[na][2], s[na][3]));
        }
        mx0 = fmaxf(mx0, __shfl_xor_sync(0xffffffffu, mx0, 1));
        mx0 = fmaxf(mx0, __shfl_xor_sync(0xffffffffu, mx0, 2));
        mx1 = fmaxf(mx1, __shfl_xor_sync(0xffffffffu, mx1, 1));
        mx1 = fmaxf(mx1, __shfl_xor_sync(0xffffffffu, mx1, 2));

        float mn0 = fmaxf(mrow[0], mx0);
        float mn1 = fmaxf(mrow[1], mx1);
        float fac0 = __expf(mrow[0] - mn0);
        float fac1 = __expf(mrow[1] - mn1);
        mrow[0] = mn0; mrow[1] = mn1;

        float sum0 = 0.0f, sum1 = 0.0f;
#pragma unroll
        for (int na = 0; na < 8; ++na) {
            s[na][0] = __expf(s[na][0] - mn0); sum0 += s[na][0];
            s[na][1] = __expf(s[na][1] - mn0); sum0 += s[na][1];
            s[na][2] = __expf(s[na][2] - mn1); sum1 += s[na][2];
            s[na][3] = __expf(s[na][3] - mn1); sum1 += s[na][3];
        }
        sum0 += __shfl_xor_sync(0xffffffffu, sum0, 1);
        sum0 += __shfl_xor_sync(0xffffffffu, sum0, 2);
        sum1 += __shfl_xor_sync(0xffffffffu, sum1, 1);
        sum1 += __shfl_xor_sync(0xffffffffu, sum1, 2);
        lrow[0] = lrow[0] * fac0 + sum0;
        lrow[1] = lrow[1] * fac1 + sum1;

#pragma unroll
        for (int na = 0; na < 8; ++na) {
            o[na][0] *= fac0; o[na][1] *= fac0;
            o[na][2] *= fac1; o[na][3] *= fac1;
        }

        // ---- store P (warp-private rows) ----
#pragma unroll
        for (int na = 0; na < 8; ++na) {
            int col = na * 8 + 2 * tig;
            *(float2*)&Ps[R * 64 + (col ^ sw)] = make_float2(s[na][0], s[na][1]);
            *(float2*)&Ps[R8 * 64 + (col ^ sw)] = make_float2(s[na][2], s[na][3]);
        }
        __syncwarp();

        // ---- O += P @ V ----
#pragma unroll
        for (int ks = 0; ks < 8; ++ks) {
            const int kva = ks * 8 + tig;
            const int kvb = kva + 4;
            uint32_t ph[4], pl[4];
            tf32_split(Ps[R * 64 + (kva ^ sw)],  ph[0], pl[0]);
            tf32_split(Ps[R8 * 64 + (kva ^ sw)], ph[1], pl[1]);
            tf32_split(Ps[R * 64 + (kvb ^ sw)],  ph[2], pl[2]);
            tf32_split(Ps[R8 * 64 + (kvb ^ sw)], ph[3], pl[3]);
            const int swa = tig << 3;
            const int swb = (tig + 4) << 3;
#pragma unroll
            for (int na = 0; na < 8; ++na) {
                int c = na * 8 + g;
                uint32_t vh[2];
                vh[0] = Vs[kva * 64 + (c ^ swa)];
                vh[1] = Vs[kvb * 64 + (c ^ swb)];
                mma_tf32(o[na], ph, vh);
                mma_tf32(o[na], pl, vh);
            }
        }
        __syncthreads();
    }

    // Epilogue: normalize and emit tf32 hi/lo planes
    float i0 = 1.0f / lrow[0];
    float i1 = 1.0f / lrow[1];
    const size_t obase = ((size_t)(b * Sq + q0) * Hq) + ho;
#pragma unroll
    for (int na = 0; na < 8; ++na) {
        int col = na * 8 + 2 * tig;
        float v0 = o[na][0] * i0, v1 = o[na][1] * i0;
        float v2 = o[na][2] * i1, v3 = o[na][3] * i1;
        uint2 h01, l01, h23, l23;
        tf32_split(v0, h01.x, l01.x);
        tf32_split(v1, h01.y, l01.y);
        tf32_split(v2, h23.x, l23.x);
        tf32_split(v3, h23.y, l23.y);
        *(uint2*)&Ohi[obase + (size_t)R * Hq + col]  = h01;
        *(uint2*)&Olo[obase + (size_t)R * Hq + col]  = l01;
        *(uint2*)&Ohi[obase + (size_t)R8 * Hq + col] = h23;
        *(uint2*)&Olo[obase + (size_t)R8 * Hq + col] = l23;
    }
}

// ---------------------------------------------------------------------------
// Launch
// ---------------------------------------------------------------------------
extern "C" void kernel_launch(void* const* d_in, const int* in_sizes, int n_in,
                              void* d_out, int out_size) {
    const float* X    = (const float*)d_in[0];
    const float* mask = (const float*)d_in[1];
    const float* cs   = (const float*)d_in[2];
    const float* sn   = (const float*)d_in[3];
    const float* Wq   = (const float*)d_in[4];
    const float* Wk   = (const float*)d_in[5];
    const float* Wv   = (const float*)d_in[6];
    const float* Wo   = (const float*)d_in[7];
    float* out = (float*)d_out;

    float *Qp, *Kp, *Vp;
    uint32_t *Xhi, *Xlo, *Ahi, *Alo, *Whq, *Whk, *Whv, *Who;
    cudaGetSymbolAddress((void**)&Qp, g_Q);
    cudaGetSymbolAddress((void**)&Kp, g_K);
    cudaGetSymbolAddress((void**)&Vp, g_V);
    cudaGetSymbolAddress((void**)&Xhi, g_Xhi);
    cudaGetSymbolAddress((void**)&Xlo, g_Xlo);
    cudaGetSymbolAddress((void**)&Ahi, g_Ahi);
    cudaGetSymbolAddress((void**)&Alo, g_Alo);
    cudaGetSymbolAddress((void**)&Whq, g_Whq);
    cudaGetSymbolAddress((void**)&Whk, g_Whk);
    cudaGetSymbolAddress((void**)&Whv, g_Whv);
    cudaGetSymbolAddress((void**)&Who, g_Who);

    const int M = Bq * Sq;                          // 4096
    const size_t shm_g = GEMM_SMEM;                 // 110,592
    const size_t shm_a = 24640u * sizeof(uint32_t); // 98,560

    static bool attr_set = false;
    if (!attr_set) {
        cudaFuncSetAttribute(gemm_pl_nt,
                             cudaFuncAttributeMaxDynamicSharedMemorySize,
                             (int)shm_g);
        cudaFuncSetAttribute(gemm_pl_qkv,
                             cudaFuncAttributeMaxDynamicSharedMemorySize,
                             (int)shm_g);
        cudaFuncSetAttribute(attn_mma,
                             cudaFuncAttributeMaxDynamicSharedMemorySize,
                             (int)shm_a);
        attr_set = true;
    }

    // Pre-pass: split X, round weights
    const int nx4 = Bq * Sq * Hq / 4;   // 2,097,152
    split_plane_kernel<<<nx4 / 256, 256>>>((const float4*)X,
                                           (uint4*)Xhi, (uint4*)Xlo, nx4);
    const int nw4 = Hq * Hq / 4;        // 1,048,576
    round_w_kernel<<<dim3(nw4 / 256, 4), 256>>>(
        (const float4*)Wq, (const float4*)Wk,
        (const float4*)Wv, (const float4*)Wo,
        (uint4*)Whq, (uint4*)Whk, (uint4*)Whv, (uint4*)Who, nw4);

    // QKV projection (fused, plane inputs)
    gemm_pl_qkv<<<dim3(48, M / 128), 256, shm_g>>>(Xhi, Xlo, Whq, Whk, Whv,
                                                   Qp, Kp, Vp);

    const int PAIRS = Bq * Sq * NHq * (HDq / 2);
    rope_kernel<<<(2 * PAIRS + 255) / 256, 256>>>(Qp, Kp, cs, sn);

    attn_mma<<<dim3(Sq / 128, NHq, Bq), 256, shm_a>>>(Qp, Kp, Vp, mask,
                                                      Ahi, Alo);

    gemm_pl_nt<<<dim3(Hq / 128, M / 128), 256, shm_g>>>(Ahi, Alo, Who, out,
                                                        M, Hq, Hq);
}

// round 11
// speedup vs baseline: 1.1156x; 1.0966x over previous
#include <cuda_runtime.h>
#include <cuda_bf16.h>
#include <cstddef>
#include <cstdint>

// Problem constants
#define Bq  2
#define Sq  2048
#define Hq  2048
#define NHq 32
#define HDq 64

// Scratch buffers
__device__ float    g_Q[Bq * Sq * Hq];
__device__ float    g_K[Bq * Sq * Hq];
__device__ float    g_V[Bq * Sq * Hq];
__device__ float    g_A[Bq * Sq * Hq];
__device__ uint32_t g_Whq[Hq * Hq];
__device__ uint32_t g_Whk[Hq * Hq];
__device__ uint32_t g_Whv[Hq * Hq];
__device__ uint32_t g_Who[Hq * Hq];

// ---------------------------------------------------------------------------
// Helpers
// ---------------------------------------------------------------------------
__device__ __forceinline__ uint32_t smem_to_u32(const void* smem_ptr) {
    uint32_t addr;
    asm("{ .reg .u64 tmp; cvta.to.shared.u64 tmp, %1; cvt.u32.u64 %0, tmp; }"
        : "=r"(addr) : "l"(smem_ptr));
    return addr;
}

__device__ __forceinline__ void tf32_split(float x, uint32_t& hi, uint32_t& lo) {
    asm("cvt.rna.tf32.f32 %0, %1;" : "=r"(hi) : "f"(x));
    float l = x - __uint_as_float(hi);
    asm("cvt.rna.tf32.f32 %0, %1;" : "=r"(lo) : "f"(l));
}

__device__ __forceinline__ uint32_t tf32_rna(float x) {
    uint32_t r;
    asm("cvt.rna.tf32.f32 %0, %1;" : "=r"(r) : "f"(x));
    return r;
}

__device__ __forceinline__ void mma_tf32(float c[4], const uint32_t a[4],
                                         const uint32_t b[2]) {
    asm volatile(
        "mma.sync.aligned.m16n8k8.row.col.f32.tf32.tf32.f32 "
        "{%0,%1,%2,%3}, {%4,%5,%6,%7}, {%8,%9}, {%0,%1,%2,%3};\n"
        : "+f"(c[0]), "+f"(c[1]), "+f"(c[2]), "+f"(c[3])
        : "r"(a[0]), "r"(a[1]), "r"(a[2]), "r"(a[3]), "r"(b[0]), "r"(b[1]));
}

#define CP_ASYNC16(dst_u32, src_ptr) \
    asm volatile("cp.async.cg.shared.global [%0], [%1], 16;" \
                 :: "r"(dst_u32), "l"(src_ptr) : "memory")
#define CP_COMMIT() asm volatile("cp.async.commit_group;" ::: "memory")
#define CP_WAIT1()  asm volatile("cp.async.wait_group 1;" ::: "memory")
#define CP_WAIT0()  asm volatile("cp.async.wait_group 0;" ::: "memory")

// ---------------------------------------------------------------------------
// Pre-pass: round the four weight matrices to single tf32 planes (one time,
// removes the 32x-redundant per-CTA W rounding from the GEMMs).
// ---------------------------------------------------------------------------
__global__ void round_w_kernel(const float4* __restrict__ w0,
                               const float4* __restrict__ w1,
                               const float4* __restrict__ w2,
                               const float4* __restrict__ w3,
                               uint4* __restrict__ d0, uint4* __restrict__ d1,
                               uint4* __restrict__ d2, uint4* __restrict__ d3,
                               int n4) {
    int i = blockIdx.x * blockDim.x + threadIdx.x;
    if (i >= n4) return;
    const float4* s = (blockIdx.y == 0) ? w0 : (blockIdx.y == 1) ? w1
                      : (blockIdx.y == 2) ? w2 : w3;
    uint4* d = (blockIdx.y == 0) ? d0 : (blockIdx.y == 1) ? d1
               : (blockIdx.y == 2) ? d2 : d3;
    float4 v = s[i];
    uint4 r;
    r.x = tf32_rna(v.x); r.y = tf32_rna(v.y);
    r.z = tf32_rna(v.z); r.w = tf32_rna(v.w);
    d[i] = r;
}

// ---------------------------------------------------------------------------
// Hybrid GEMM (NT): C[m][n] = sum_k A[m][k] * W[n][k].
// A fp32 (split to tf32 hi/lo in-kernel, R7 layout: [k][m^swz], stride 136).
// W pre-rounded tf32 plane, fetched by cp.async into row-major [n][36] smem,
// double-buffered. 2-mma per k-step (Ahi*B, Alo*B). 256 thr, warp tile 64x32.
// __launch_bounds__(256,2): 2 CTAs/SM (smem 71,680 B/CTA).
// ---------------------------------------------------------------------------
#define AW 4352               // words per A plane (32*136)
#define BW 4608               // words per B stage (128*36)
#define GEMM_SMEM ((2 * AW + 2 * BW) * 4)   // 71,680 B

__device__ __forceinline__ void gemm_hy_core(uint32_t* sm,
        const float* __restrict__ A,
        const uint32_t* __restrict__ Wpl,
        float* __restrict__ C, int M, int N, int K, int m0, int n0) {
    uint32_t* Ahi = sm;
    uint32_t* Alo = sm + AW;

    const int tid  = threadIdx.x;
    const int lane = tid & 31;
    const int wid  = tid >> 5;
    const int wm   = (wid & 1) * 64;
    const int wn   = (wid >> 1) * 32;
    const int g    = lane >> 2;
    const int tig  = lane & 3;

    // A loader mapping (R7): each thread loads 4 float4 per chunk
    const int lm = tid >> 3;           // 0..31
    const int lk = (tid & 7) * 4;      // 0..28
    const float* Ag = A + (size_t)(m0 + lm) * K + lk;

    // B loader mapping: 2 threads per row, 4 x 16B each
    const int lrB = tid >> 1;          // 0..127
    const int lkb = tid & 1;           // 0..1
    const uint32_t* srcB = Wpl + (size_t)(n0 + lrB) * K;
    const uint32_t sm_base = smem_to_u32(sm);
    const uint32_t bbase = sm_base + (uint32_t)(2 * AW + lrB * 36) * 4u;

    auto issueB = [&](int stage, int ch) {
        const uint32_t* src = srcB + ch * 32;
        uint32_t dst = bbase + (uint32_t)(stage * BW) * 4u;
#pragma unroll
        for (int i = 0; i < 4; ++i) {
            int kg = lkb + 2 * i;
            CP_ASYNC16(dst + kg * 16, src + kg * 4);
        }
        CP_COMMIT();
    };

    float acc[4][4][4];
#pragma unroll
    for (int i = 0; i < 4; ++i)
#pragma unroll
        for (int j = 0; j < 4; ++j)
#pragma unroll
            for (int r = 0; r < 4; ++r) acc[i][j][r] = 0.0f;

    // Prefetch chunk 0: B via cp.async, A into registers
    issueB(0, 0);
    float4 pa[4];
#pragma unroll
    for (int it = 0; it < 4; ++it)
        pa[it] = *(const float4*)(Ag + (size_t)it * 32 * K);

    const int NCH = K >> 5;
    for (int ch = 0; ch < NCH; ++ch) {
        const int s = ch & 1;

        // Split + transpose-store A chunk (R7 layout)
#pragma unroll
        for (int it = 0; it < 4; ++it) {
            int m = lm + it * 32;
            float va[4] = {pa[it].x, pa[it].y, pa[it].z, pa[it].w};
#pragma unroll
            for (int u = 0; u < 4; ++u) {
                int k   = lk + u;
                int col = m ^ (k & 28);
                uint32_t h, l;
                tf32_split(va[u], h, l);
                Ahi[k * 136 + col] = h;
                Alo[k * 136 + col] = l;
            }
        }

        // Prefetch next B stage, then wait for this one
        if (ch + 1 < NCH) {
            issueB(s ^ 1, ch + 1);
            CP_WAIT1();
        } else {
            CP_WAIT0();
        }
        __syncthreads();

        // Prefetch next A chunk into registers (overlaps mma)
        if (ch + 1 < NCH) {
            const float* Ap = Ag + (size_t)(ch + 1) * 32;
#pragma unroll
            for (int it = 0; it < 4; ++it)
                pa[it] = *(const float4*)(Ap + (size_t)it * 32 * K);
        }

        const uint32_t* sB = sm + 2 * AW + s * BW;

#pragma unroll
        for (int ks = 0; ks < 4; ++ks) {
            const int ka  = ks * 8 + tig;
            const int kb  = ka + 4;
            const int swa = ka & 28;
            const int swb = kb & 28;

            uint32_t ah[4][4], al[4][4];
#pragma unroll
            for (int ma = 0; ma < 4; ++ma) {
                int r0 = wm + ma * 16 + g;
                int r1 = r0 + 8;
                ah[ma][0] = Ahi[ka * 136 + (r0 ^ swa)];
                ah[ma][1] = Ahi[ka * 136 + (r1 ^ swa)];
                ah[ma][2] = Ahi[kb * 136 + (r0 ^ swb)];
                ah[ma][3] = Ahi[kb * 136 + (r1 ^ swb)];
                al[ma][0] = Alo[ka * 136 + (r0 ^ swa)];
                al[ma][1] = Alo[ka * 136 + (r1 ^ swa)];
                al[ma][2] = Alo[kb * 136 + (r0 ^ swb)];
                al[ma][3] = Alo[kb * 136 + (r1 ^ swb)];
            }
            uint32_t bh[4][2];
#pragma unroll
            for (int na = 0; na < 4; ++na) {
                int c = (wn + na * 8 + g) * 36;
                bh[na][0] = sB[c + ka];
                bh[na][1] = sB[c + kb];
            }
#pragma unroll
            for (int ma = 0; ma < 4; ++ma)
#pragma unroll
                for (int na = 0; na < 4; ++na) {
                    mma_tf32(acc[ma][na], ah[ma], bh[na]);
                    mma_tf32(acc[ma][na], al[ma], bh[na]);
                }
        }
        __syncthreads();
    }

#pragma unroll
    for (int ma = 0; ma < 4; ++ma) {
        int r0 = m0 + wm + ma * 16 + g;
#pragma unroll
        for (int na = 0; na < 4; ++na) {
            int c = n0 + wn + na * 8 + 2 * tig;
            *(float2*)&C[(size_t)r0 * N + c] =
                make_float2(acc[ma][na][0], acc[ma][na][1]);
            *(float2*)&C[(size_t)(r0 + 8) * N + c] =
                make_float2(acc[ma][na][2], acc[ma][na][3]);
        }
    }
}

__global__ __launch_bounds__(256, 2)
void gemm_hy_nt(const float* __restrict__ A, const uint32_t* __restrict__ Wpl,
                float* __restrict__ C, int M, int N, int K) {
    extern __shared__ uint32_t smg[];
    gemm_hy_core(smg, A, Wpl, C, M, N, K, blockIdx.y * 128, blockIdx.x * 128);
}

// Fused QKV: blockIdx.x in [0,48): selects W plane and output buffer.
__global__ __launch_bounds__(256, 2)
void gemm_hy_qkv(const float* __restrict__ X,
                 const uint32_t* __restrict__ Whq,
                 const uint32_t* __restrict__ Whk,
                 const uint32_t* __restrict__ Whv,
                 float* __restrict__ Qo, float* __restrict__ Ko,
                 float* __restrict__ Vo) {
    extern __shared__ uint32_t smg[];
    const int which = blockIdx.x >> 4;
    const uint32_t* W = (which == 0) ? Whq : (which == 1) ? Whk : Whv;
    float* C = (which == 0) ? Qo : (which == 1) ? Ko : Vo;
    gemm_hy_core(smg, X, W, C, Bq * Sq, Hq, Hq,
                 blockIdx.y * 128, (blockIdx.x & 15) * 128);
}

// ---------------------------------------------------------------------------
// RoPE (in-place) on Q and K. Q also folded with 1/sqrt(HD) = 0.125.
// ---------------------------------------------------------------------------
__global__ void rope_kernel(float* __restrict__ Q, float* __restrict__ K,
                            const float* __restrict__ cs,
                            const float* __restrict__ sn) {
    const int PAIRS = Bq * Sq * NHq * (HDq / 2);
    int idx = blockIdx.x * blockDim.x + threadIdx.x;
    if (idx >= 2 * PAIRS) return;
    bool isQ = idx < PAIRS;
    int p = isQ ? idx : idx - PAIRS;

    int d = p & 31;
    int h = (p >> 5) & 31;
    int s = (p >> 10) & 2047;
    int b = p >> 21;

    size_t base = ((size_t)(b * Sq + s) * Hq) + (size_t)h * HDq + d;
    float c1 = cs[s * HDq + d],      s1 = sn[s * HDq + d];
    float c2 = cs[s * HDq + d + 32], s2 = sn[s * HDq + d + 32];

    float* T = isQ ? Q : K;
    float scale = isQ ? 0.125f : 1.0f;
    float x1 = T[base];
    float x2 = T[base + 32];
    T[base]      = (x1 * c1 - x2 * s1) * scale;
    T[base + 32] = (x2 * c2 + x1 * s2) * scale;
}

// ---------------------------------------------------------------------------
// Flash attention on tensor cores, 2-mma tf32 split (R7-validated, float out).
// ---------------------------------------------------------------------------
__global__ __launch_bounds__(256, 2)
void attn_mma(const float* __restrict__ Q, const float* __restrict__ K,
              const float* __restrict__ V, const float* __restrict__ mask,
              float* __restrict__ O) {
    extern __shared__ uint32_t sma[];
    float*    Qs  = (float*)sma;          // 8192 floats
    uint32_t* Ks  = sma + 8192;           // 4096 (tf32 bits)
    uint32_t* Vs  = sma + 12288;          // 4096 (tf32 bits)
    float*    Ps  = (float*)(sma + 16384);// 8192 floats
    float*    msk = (float*)(sma + 24576);// 64

    const int tid  = threadIdx.x;
    const int lane = tid & 31;
    const int wid  = tid >> 5;
    const int g    = lane >> 2;
    const int tig  = lane & 3;
    const int R    = wid * 16 + g;
    const int R8   = R + 8;
    const int sw   = g << 2;

    const int b  = blockIdx.z;
    const int h  = blockIdx.y;
    const int q0 = blockIdx.x * 128;
    const size_t ho = (size_t)h * HDq;

    const float* Qb = Q + ((size_t)(b * Sq + q0) * Hq) + ho;
#pragma unroll
    for (int it = 0; it < 8; ++it) {
        int f = tid + it * 256;
        int r = f >> 4, d0 = (f & 15) << 2;
        float4 v = *(const float4*)(Qb + (size_t)r * Hq + d0);
        *(float4*)&Qs[r * 64 + (d0 ^ ((r & 7) << 2))] = v;
    }

    float o[8][4];
#pragma unroll
    for (int na = 0; na < 8; ++na)
#pragma unroll
        for (int e = 0; e < 4; ++e) o[na][e] = 0.0f;
    float mrow[2] = {-1e30f, -1e30f};
    float lrow[2] = {0.0f, 0.0f};

    for (int t = 0; t < Sq / 64; ++t) {
        const int c0 = t * 64;
        const float* Kb = K + ((size_t)(b * Sq + c0) * Hq) + ho;
        const float* Vb = V + ((size_t)(b * Sq + c0) * Hq) + ho;
#pragma unroll
        for (int it = 0; it < 4; ++it) {
            int f = tid + it * 256;
            int r = f >> 4, d0 = (f & 15) << 2;
            float4 kv = *(const float4*)(Kb + (size_t)r * Hq + d0);
            uint4 kq;
            kq.x = tf32_rna(kv.x); kq.y = tf32_rna(kv.y);
            kq.z = tf32_rna(kv.z); kq.w = tf32_rna(kv.w);
            *(uint4*)&Ks[r * 64 + (d0 ^ ((r & 7) << 2))] = kq;
            float4 vv = *(const float4*)(Vb + (size_t)r * Hq + d0);
            uint4 vq;
            vq.x = tf32_rna(vv.x); vq.y = tf32_rna(vv.y);
            vq.z = tf32_rna(vv.z); vq.w = tf32_rna(vv.w);
            *(uint4*)&Vs[r * 64 + (d0 ^ ((r & 7) << 3))] = vq;
        }
        if (tid < 16)
            *(float4*)&msk[tid * 4] =
                *(const float4*)(mask + (size_t)b * Sq + c0 + tid * 4);
        __syncthreads();

        // ---- S = Q @ K^T ----
        float s[8][4];
#pragma unroll
        for (int na = 0; na < 8; ++na)
#pragma unroll
            for (int e = 0; e < 4; ++e) s[na][e] = 0.0f;

#pragma unroll
        for (int ks = 0; ks < 8; ++ks) {
            const int ka = ks * 8 + tig;
            const int kb2 = ka + 4;
            uint32_t ah[4], al[4];
            tf32_split(Qs[R * 64 + (ka ^ sw)],  ah[0], al[0]);
            tf32_split(Qs[R8 * 64 + (ka ^ sw)], ah[1], al[1]);
            tf32_split(Qs[R * 64 + (kb2 ^ sw)], ah[2], al[2]);
            tf32_split(Qs[R8 * 64 + (kb2 ^ sw)], ah[3], al[3]);
#pragma unroll
            for (int na = 0; na < 8; ++na) {
                int c = na * 8 + g;
                uint32_t bh[2];
                bh[0] = Ks[c * 64 + (ka ^ sw)];
                bh[1] = Ks[c * 64 + (kb2 ^ sw)];
                mma_tf32(s[na], ah, bh);
                mma_tf32(s[na], al, bh);
            }
        }

        // ---- mask + online softmax ----
#pragma unroll
        for (int na = 0; na < 8; ++na) {
            float m0 = msk[na * 8 + 2 * tig];
            float m1 = msk[na * 8 + 2 * tig + 1];
            s[na][0] += m0; s[na][1] += m1;
            s[na][2] += m0; s[na][3] += m1;
        }

        float mx0 = -1e30f, mx1 = -1e30f;
#pragma unroll
        for (int na = 0; na < 8; ++na) {
            mx0 = fmaxf(mx0, fmaxf(s[na][0], s[na][1]));
            mx1 = fmaxf(mx1, fmaxf(s[na][2], s[na][3]));
        }
        mx0 = fmaxf(mx0, __shfl_xor_sync(0xffffffffu, mx0, 1));
        mx0 = fmaxf(mx0, __shfl_xor_sync(0xffffffffu, mx0, 2));
        mx1 = fmaxf(mx1, __shfl_xor_sync(0xffffffffu, mx1, 1));
        mx1 = fmaxf(mx1, __shfl_xor_sync(0xffffffffu, mx1, 2));

        float mn0 = fmaxf(mrow[0], mx0);
        float mn1 = fmaxf(mrow[1], mx1);
        float fac0 = __expf(mrow[0] - mn0);
        float fac1 = __expf(mrow[1] - mn1);
        mrow[0] = mn0; mrow[1] = mn1;

        float sum0 = 0.0f, sum1 = 0.0f;
#pragma unroll
        for (int na = 0; na < 8; ++na) {
            s[na][0] = __expf(s[na][0] - mn0); sum0 += s[na][0];
            s[na][1] = __expf(s[na][1] - mn0); sum0 += s[na][1];
            s[na][2] = __expf(s[na][2] - mn1); sum1 += s[na][2];
            s[na][3] = __expf(s[na][3] - mn1); sum1 += s[na][3];
        }
        sum0 += __shfl_xor_sync(0xffffffffu, sum0, 1);
        sum0 += __shfl_xor_sync(0xffffffffu, sum0, 2);
        sum1 += __shfl_xor_sync(0xffffffffu, sum1, 1);
        sum1 += __shfl_xor_sync(0xffffffffu, sum1, 2);
        lrow[0] = lrow[0] * fac0 + sum0;
        lrow[1] = lrow[1] * fac1 + sum1;

#pragma unroll
        for (int na = 0; na < 8; ++na) {
            o[na][0] *= fac0; o[na][1] *= fac0;
            o[na][2] *= fac1; o[na][3] *= fac1;
        }

        // ---- store P (warp-private rows) ----
#pragma unroll
        for (int na = 0; na < 8; ++na) {
            int col = na * 8 + 2 * tig;
            *(float2*)&Ps[R * 64 + (col ^ sw)] = make_float2(s[na][0], s[na][1]);
            *(float2*)&Ps[R8 * 64 + (col ^ sw)] = make_float2(s[na][2], s[na][3]);
        }
        __syncwarp();

        // ---- O += P @ V ----
#pragma unroll
        for (int ks = 0; ks < 8; ++ks) {
            const int kva = ks * 8 + tig;
            const int kvb = kva + 4;
            uint32_t ph[4], pl[4];
            tf32_split(Ps[R * 64 + (kva ^ sw)],  ph[0], pl[0]);
            tf32_split(Ps[R8 * 64 + (kva ^ sw)], ph[1], pl[1]);
            tf32_split(Ps[R * 64 + (kvb ^ sw)],  ph[2], pl[2]);
            tf32_split(Ps[R8 * 64 + (kvb ^ sw)], ph[3], pl[3]);
            const int swa = tig << 3;
            const int swb = (tig + 4) << 3;
#pragma unroll
            for (int na = 0; na < 8; ++na) {
                int c = na * 8 + g;
                uint32_t vh[2];
                vh[0] = Vs[kva * 64 + (c ^ swa)];
                vh[1] = Vs[kvb * 64 + (c ^ swb)];
                mma_tf32(o[na], ph, vh);
                mma_tf32(o[na], pl, vh);
            }
        }
        __syncthreads();
    }

    // Epilogue
    float i0 = 1.0f / lrow[0];
    float i1 = 1.0f / lrow[1];
    float* Ob = O + ((size_t)(b * Sq + q0) * Hq) + ho;
#pragma unroll
    for (int na = 0; na < 8; ++na) {
        int col = na * 8 + 2 * tig;
        *(float2*)&Ob[(size_t)R * Hq + col] =
            make_float2(o[na][0] * i0, o[na][1] * i0);
        *(float2*)&Ob[(size_t)R8 * Hq + col] =
            make_float2(o[na][2] * i1, o[na][3] * i1);
    }
}

// ---------------------------------------------------------------------------
// Launch
// ---------------------------------------------------------------------------
extern "C" void kernel_launch(void* const* d_in, const int* in_sizes, int n_in,
                              void* d_out, int out_size) {
    const float* X    = (const float*)d_in[0];
    const float* mask = (const float*)d_in[1];
    const float* cs   = (const float*)d_in[2];
    const float* sn   = (const float*)d_in[3];
    const float* Wq   = (const float*)d_in[4];
    const float* Wk   = (const float*)d_in[5];
    const float* Wv   = (const float*)d_in[6];
    const float* Wo   = (const float*)d_in[7];
    float* out = (float*)d_out;

    float *Qp, *Kp, *Vp, *Ap;
    uint32_t *Whq, *Whk, *Whv, *Who;
    cudaGetSymbolAddress((void**)&Qp, g_Q);
    cudaGetSymbolAddress((void**)&Kp, g_K);
    cudaGetSymbolAddress((void**)&Vp, g_V);
    cudaGetSymbolAddress((void**)&Ap, g_A);
    cudaGetSymbolAddress((void**)&Whq, g_Whq);
    cudaGetSymbolAddress((void**)&Whk, g_Whk);
    cudaGetSymbolAddress((void**)&Whv, g_Whv);
    cudaGetSymbolAddress((void**)&Who, g_Who);

    const int M = Bq * Sq;                          // 4096
    const size_t shm_g = GEMM_SMEM;                 // 71,680
    const size_t shm_a = 24640u * sizeof(uint32_t); // 98,560

    static bool attr_set = false;
    if (!attr_set) {
        cudaFuncSetAttribute(gemm_hy_nt,
                             cudaFuncAttributeMaxDynamicSharedMemorySize,
                             (int)shm_g);
        cudaFuncSetAttribute(gemm_hy_qkv,
                             cudaFuncAttributeMaxDynamicSharedMemorySize,
                             (int)shm_g);
        cudaFuncSetAttribute(attn_mma,
                             cudaFuncAttributeMaxDynamicSharedMemorySize,
                             (int)shm_a);
        attr_set = true;
    }

    // Pre-pass: round weights to tf32 planes
    const int nw4 = Hq * Hq / 4;        // 1,048,576
    round_w_kernel<<<dim3(nw4 / 256, 4), 256>>>(
        (const float4*)Wq, (const float4*)Wk,
        (const float4*)Wv, (const float4*)Wo,
        (uint4*)Whq, (uint4*)Whk, (uint4*)Whv, (uint4*)Who, nw4);

    // QKV projection (fused)
    gemm_hy_qkv<<<dim3(48, M / 128), 256, shm_g>>>(X, Whq, Whk, Whv,
                                                   Qp, Kp, Vp);

    const int PAIRS = Bq * Sq * NHq * (HDq / 2);
    rope_kernel<<<(2 * PAIRS + 255) / 256, 256>>>(Qp, Kp, cs, sn);

    attn_mma<<<dim3(Sq / 128, NHq, Bq), 256, shm_a>>>(Qp, Kp, Vp, mask, Ap);

    gemm_hy_nt<<<dim3(Hq / 128, M / 128), 256, shm_g>>>(Ap, Who, out,
                                                        M, Hq, Hq);
}

// round 12
// speedup vs baseline: 1.3988x; 1.2539x over previous
#include <cuda_runtime.h>
#include <cuda_bf16.h>
#include <cstddef>
#include <cstdint>

// Problem constants
#define Bq  2
#define Sq  2048
#define Hq  2048
#define NHq 32
#define HDq 64

// Scratch buffers
__device__ float    g_Q[Bq * Sq * Hq];
__device__ float    g_K[Bq * Sq * Hq];
__device__ float    g_V[Bq * Sq * Hq];
__device__ float    g_A[Bq * Sq * Hq];
// Packed bf16 hi/lo weight planes: [n][K/2] uint32 (2 bf16 per word)
__device__ uint32_t g_Wh[4][Hq * Hq / 2];
__device__ uint32_t g_Wl[4][Hq * Hq / 2];

// ---------------------------------------------------------------------------
// Helpers
// ---------------------------------------------------------------------------
__device__ __forceinline__ uint32_t tf32_rna(float x) {
    uint32_t r;
    asm("cvt.rna.tf32.f32 %0, %1;" : "=r"(r) : "f"(x));
    return r;
}

__device__ __forceinline__ void tf32_split(float x, uint32_t& hi, uint32_t& lo) {
    asm("cvt.rna.tf32.f32 %0, %1;" : "=r"(hi) : "f"(x));
    float l = x - __uint_as_float(hi);
    asm("cvt.rna.tf32.f32 %0, %1;" : "=r"(lo) : "f"(l));
}

// Pack two floats to bf16x2: result low16 = lo_elem (k), high16 = hi_elem (k+1)
__device__ __forceinline__ uint32_t bf16x2_pack(float hi_elem, float lo_elem) {
    uint32_t r;
    asm("cvt.rn.bf16x2.f32 %0, %1, %2;" : "=r"(r) : "f"(hi_elem), "f"(lo_elem));
    return r;
}

__device__ __forceinline__ void mma_tf32(float c[4], const uint32_t a[4],
                                         const uint32_t b[2]) {
    asm volatile(
        "mma.sync.aligned.m16n8k8.row.col.f32.tf32.tf32.f32 "
        "{%0,%1,%2,%3}, {%4,%5,%6,%7}, {%8,%9}, {%0,%1,%2,%3};\n"
        : "+f"(c[0]), "+f"(c[1]), "+f"(c[2]), "+f"(c[3])
        : "r"(a[0]), "r"(a[1]), "r"(a[2]), "r"(a[3]), "r"(b[0]), "r"(b[1]));
}

__device__ __forceinline__ void mma_bf16(float c[4], const uint32_t a[4],
                                         const uint32_t b[2]) {
    asm volatile(
        "mma.sync.aligned.m16n8k16.row.col.f32.bf16.bf16.f32 "
        "{%0,%1,%2,%3}, {%4,%5,%6,%7}, {%8,%9}, {%0,%1,%2,%3};\n"
        : "+f"(c[0]), "+f"(c[1]), "+f"(c[2]), "+f"(c[3])
        : "r"(a[0]), "r"(a[1]), "r"(a[2]), "r"(a[3]), "r"(b[0]), "r"(b[1]));
}

// Row-dependent column rotation for the [row][16] packed-k2 smem layout.
#define FROT(m) ((((m) >> 1) & 3) << 2)

// ---------------------------------------------------------------------------
// Pre-pass: split all four W matrices into packed bf16 hi/lo planes.
// Each float4 (4 consecutive k) -> uint2 hi + uint2 lo at the same flat index.
// ---------------------------------------------------------------------------
__global__ void split_w_bf16(const float4* __restrict__ w0,
                             const float4* __restrict__ w1,
                             const float4* __restrict__ w2,
                             const float4* __restrict__ w3, int n4) {
    int i = blockIdx.x * blockDim.x + threadIdx.x;
    if (i >= n4) return;
    const float4* s = (blockIdx.y == 0) ? w0 : (blockIdx.y == 1) ? w1
                      : (blockIdx.y == 2) ? w2 : w3;
    float4 v = s[i];
    uint32_t h0 = bf16x2_pack(v.y, v.x);
    uint32_t h1 = bf16x2_pack(v.w, v.z);
    float r0 = v.x - __uint_as_float(h0 << 16);
    float r1 = v.y - __uint_as_float(h0 & 0xFFFF0000u);
    float r2 = v.z - __uint_as_float(h1 << 16);
    float r3 = v.w - __uint_as_float(h1 & 0xFFFF0000u);
    uint32_t l0 = bf16x2_pack(r1, r0);
    uint32_t l1 = bf16x2_pack(r3, r2);
    ((uint2*)g_Wh[blockIdx.y])[i] = make_uint2(h0, h1);
    ((uint2*)g_Wl[blockIdx.y])[i] = make_uint2(l0, l1);
}

// ---------------------------------------------------------------------------
// bf16 3-mma GEMM (NT): C[m][n] = sum_k A[m][k] * W[n][k]
// A fp32 split to bf16 hi/lo in-kernel; W pre-split planes loaded directly.
// Block tile 128x128, K-chunk 32 (16 packed words), 256 thr, warp tile 64x32.
// Smem: 4 planes [128][16] uint32 (32 KB), col = k2 ^ FROT(row):
// stores (uint2/uint4) and all fragment LDS verified conflict-free.
// ---------------------------------------------------------------------------
#define GP 2048   // words per plane (128*16)

__device__ __forceinline__ void gemm_bf3_core(uint32_t* sm,
        const float* __restrict__ A,
        const uint32_t* __restrict__ Wh, const uint32_t* __restrict__ Wl,
        float* __restrict__ C, int M, int N, int K, int m0, int n0) {
    uint32_t* Ah = sm;
    uint32_t* Al = sm + GP;
    uint32_t* Bh = sm + 2 * GP;
    uint32_t* Bl = sm + 3 * GP;

    const int tid  = threadIdx.x;
    const int lane = tid & 31;
    const int wid  = tid >> 5;
    const int wm   = (wid & 1) * 64;
    const int wn   = (wid >> 1) * 32;
    const int g    = lane >> 2;
    const int tig  = lane & 3;

    // A loader: 4 rows spaced 32, 4 consecutive k each
    const int lm = tid >> 3;           // 0..31
    const int lk = (tid & 7) * 4;      // 0..28
    const int fa = FROT(lm);           // invariant across +32 row steps
    const float* Ag = A + (size_t)(m0 + lm) * K + lk;

    // B loader: 1 row per 2 threads, 8 packed words each
    const int nb = tid >> 1;           // 0..127
    const int hb = tid & 1;            // 0..1
    const int fb = FROT(nb);
    const int KW = K >> 1;             // packed words per row
    const uint32_t* Bhg = Wh + (size_t)(n0 + nb) * KW + 8 * hb;
    const uint32_t* Blg = Wl + (size_t)(n0 + nb) * KW + 8 * hb;

    float acc[4][4][4];
#pragma unroll
    for (int i = 0; i < 4; ++i)
#pragma unroll
        for (int j = 0; j < 4; ++j)
#pragma unroll
            for (int r = 0; r < 4; ++r) acc[i][j][r] = 0.0f;

    // Prefetch chunk 0
    float4 pa[4];
    uint4  pwh[2], pwl[2];
#pragma unroll
    for (int it = 0; it < 4; ++it)
        pa[it] = *(const float4*)(Ag + (size_t)it * 32 * K);
#pragma unroll
    for (int v = 0; v < 2; ++v) {
        pwh[v] = *(const uint4*)(Bhg + 4 * v);
        pwl[v] = *(const uint4*)(Blg + 4 * v);
    }

    const int NCH = K >> 5;
    for (int ch = 0; ch < NCH; ++ch) {
        // ---- store stage ----
        {
            const int k2 = lk >> 1;            // even
            const int colA = k2 ^ fa;
#pragma unroll
            for (int it = 0; it < 4; ++it) {
                int m = lm + it * 32;
                float4 v = pa[it];
                uint32_t h0 = bf16x2_pack(v.y, v.x);
                uint32_t h1 = bf16x2_pack(v.w, v.z);
                float r0 = v.x - __uint_as_float(h0 << 16);
                float r1 = v.y - __uint_as_float(h0 & 0xFFFF0000u);
                float r2 = v.z - __uint_as_float(h1 << 16);
                float r3 = v.w - __uint_as_float(h1 & 0xFFFF0000u);
                uint32_t l0 = bf16x2_pack(r1, r0);
                uint32_t l1 = bf16x2_pack(r3, r2);
                *(uint2*)&Ah[m * 16 + colA] = make_uint2(h0, h1);
                *(uint2*)&Al[m * 16 + colA] = make_uint2(l0, l1);
            }
#pragma unroll
            for (int v = 0; v < 2; ++v) {
                int colB = (8 * hb + 4 * v) ^ fb;
                *(uint4*)&Bh[nb * 16 + colB] = pwh[v];
                *(uint4*)&Bl[nb * 16 + colB] = pwl[v];
            }
        }
        __syncthreads();

        // ---- prefetch next chunk ----
        if (ch + 1 < NCH) {
            const float* Ap = Ag + (size_t)(ch + 1) * 32;
            const uint32_t* Bhp = Bhg + (size_t)(ch + 1) * 16;
            const uint32_t* Blp = Blg + (size_t)(ch + 1) * 16;
#pragma unroll
            for (int it = 0; it < 4; ++it)
                pa[it] = *(const float4*)(Ap + (size_t)it * 32 * K);
#pragma unroll
            for (int v = 0; v < 2; ++v) {
                pwh[v] = *(const uint4*)(Bhp + 4 * v);
                pwl[v] = *(const uint4*)(Blp + 4 * v);
            }
        }

        // ---- mma: 2 k-steps of m16n8k16 ----
#pragma unroll
        for (int ks = 0; ks < 2; ++ks) {
            const int kc = tig + 8 * ks;

            uint32_t ah[4][4], al[4][4];
#pragma unroll
            for (int ma = 0; ma < 4; ++ma) {
                int m = wm + ma * 16 + g;
                int off = m * 16 + (kc ^ FROT(m));
                ah[ma][0] = Ah[off];
                ah[ma][1] = Ah[off + 128];
                ah[ma][2] = Ah[off ^ 4];
                ah[ma][3] = Ah[(off ^ 4) + 128];
                al[ma][0] = Al[off];
                al[ma][1] = Al[off + 128];
                al[ma][2] = Al[off ^ 4];
                al[ma][3] = Al[(off ^ 4) + 128];
            }
#pragma unroll
            for (int na = 0; na < 4; ++na) {
                int n = wn + na * 8 + g;
                int offb = n * 16 + (kc ^ FROT(n));
                uint32_t bh[2], bl[2];
                bh[0] = Bh[offb];
                bh[1] = Bh[offb ^ 4];
                bl[0] = Bl[offb];
                bl[1] = Bl[offb ^ 4];
#pragma unroll
                for (int ma = 0; ma < 4; ++ma) {
                    mma_bf16(acc[ma][na], ah[ma], bh);
                    mma_bf16(acc[ma][na], al[ma], bh);
                    mma_bf16(acc[ma][na], ah[ma], bl);
                }
            }
        }
        __syncthreads();
    }

    // Epilogue
#pragma unroll
    for (int ma = 0; ma < 4; ++ma) {
        int r0 = m0 + wm + ma * 16 + g;
#pragma unroll
        for (int na = 0; na < 4; ++na) {
            int c = n0 + wn + na * 8 + 2 * tig;
            *(float2*)&C[(size_t)r0 * N + c] =
                make_float2(acc[ma][na][0], acc[ma][na][1]);
            *(float2*)&C[(size_t)(r0 + 8) * N + c] =
                make_float2(acc[ma][na][2], acc[ma][na][3]);
        }
    }
}

__global__ void gemm_bf3_o(const float* __restrict__ A,
                           float* __restrict__ C) {
    extern __shared__ uint32_t smg[];
    gemm_bf3_core(smg, A, g_Wh[3], g_Wl[3], C, Bq * Sq, Hq, Hq,
                  blockIdx.y * 128, blockIdx.x * 128);
}

// Fused QKV: blockIdx.x in [0,48): selects W plane and output buffer.
__global__ void gemm_bf3_qkv(const float* __restrict__ X,
                             float* __restrict__ Qo, float* __restrict__ Ko,
                             float* __restrict__ Vo) {
    extern __shared__ uint32_t smg[];
    const int which = blockIdx.x >> 4;
    float* C = (which == 0) ? Qo : (which == 1) ? Ko : Vo;
    gemm_bf3_core(smg, X, g_Wh[which], g_Wl[which], C, Bq * Sq, Hq, Hq,
                  blockIdx.y * 128, (blockIdx.x & 15) * 128);
}

// ---------------------------------------------------------------------------
// RoPE (in-place) on Q and K. Q also folded with 1/sqrt(HD) = 0.125.
// ---------------------------------------------------------------------------
__global__ void rope_kernel(float* __restrict__ Q, float* __restrict__ K,
                            const float* __restrict__ cs,
                            const float* __restrict__ sn) {
    const int PAIRS = Bq * Sq * NHq * (HDq / 2);
    int idx = blockIdx.x * blockDim.x + threadIdx.x;
    if (idx >= 2 * PAIRS) return;
    bool isQ = idx < PAIRS;
    int p = isQ ? idx : idx - PAIRS;

    int d = p & 31;
    int h = (p >> 5) & 31;
    int s = (p >> 10) & 2047;
    int b = p >> 21;

    size_t base = ((size_t)(b * Sq + s) * Hq) + (size_t)h * HDq + d;
    float c1 = cs[s * HDq + d],      s1 = sn[s * HDq + d];
    float c2 = cs[s * HDq + d + 32], s2 = sn[s * HDq + d + 32];

    float* T = isQ ? Q : K;
    float scale = isQ ? 0.125f : 1.0f;
    float x1 = T[base];
    float x2 = T[base + 32];
    T[base]      = (x1 * c1 - x2 * s1) * scale;
    T[base + 32] = (x2 * c2 + x1 * s2) * scale;
}

// ---------------------------------------------------------------------------
// Flash attention on tensor cores, 2-mma tf32 split (R7-validated, unchanged).
// ---------------------------------------------------------------------------
__global__ __launch_bounds__(256, 2)
void attn_mma(const float* __restrict__ Q, const float* __restrict__ K,
              const float* __restrict__ V, const float* __restrict__ mask,
              float* __restrict__ O) {
    extern __shared__ uint32_t sma[];
    float*    Qs  = (float*)sma;          // 8192 floats
    uint32_t* Ks  = sma + 8192;           // 4096 (tf32 bits)
    uint32_t* Vs  = sma + 12288;          // 4096 (tf32 bits)
    float*    Ps  = (float*)(sma + 16384);// 8192 floats
    float*    msk = (float*)(sma + 24576);// 64

    const int tid  = threadIdx.x;
    const int lane = tid & 31;
    const int wid  = tid >> 5;
    const int g    = lane >> 2;
    const int tig  = lane & 3;
    const int R    = wid * 16 + g;
    const int R8   = R + 8;
    const int sw   = g << 2;

    const int b  = blockIdx.z;
    const int h  = blockIdx.y;
    const int q0 = blockIdx.x * 128;
    const size_t ho = (size_t)h * HDq;

    const float* Qb = Q + ((size_t)(b * Sq + q0) * Hq) + ho;
#pragma unroll
    for (int it = 0; it < 8; ++it) {
        int f = tid + it * 256;
        int r = f >> 4, d0 = (f & 15) << 2;
        float4 v = *(const float4*)(Qb + (size_t)r * Hq + d0);
        *(float4*)&Qs[r * 64 + (d0 ^ ((r & 7) << 2))] = v;
    }

    float o[8][4];
#pragma unroll
    for (int na = 0; na < 8; ++na)
#pragma unroll
        for (int e = 0; e < 4; ++e) o[na][e] = 0.0f;
    float mrow[2] = {-1e30f, -1e30f};
    float lrow[2] = {0.0f, 0.0f};

    for (int t = 0; t < Sq / 64; ++t) {
        const int c0 = t * 64;
        const float* Kb = K + ((size_t)(b * Sq + c0) * Hq) + ho;
        const float* Vb = V + ((size_t)(b * Sq + c0) * Hq) + ho;
#pragma unroll
        for (int it = 0; it < 4; ++it) {
            int f = tid + it * 256;
            int r = f >> 4, d0 = (f & 15) << 2;
            float4 kv = *(const float4*)(Kb + (size_t)r * Hq + d0);
            uint4 kq;
            kq.x = tf32_rna(kv.x); kq.y = tf32_rna(kv.y);
            kq.z = tf32_rna(kv.z); kq.w = tf32_rna(kv.w);
            *(uint4*)&Ks[r * 64 + (d0 ^ ((r & 7) << 2))] = kq;
            float4 vv = *(const float4*)(Vb + (size_t)r * Hq + d0);
            uint4 vq;
            vq.x = tf32_rna(vv.x); vq.y = tf32_rna(vv.y);
            vq.z = tf32_rna(vv.z); vq.w = tf32_rna(vv.w);
            *(uint4*)&Vs[r * 64 + (d0 ^ ((r & 7) << 3))] = vq;
        }
        if (tid < 16)
            *(float4*)&msk[tid * 4] =
                *(const float4*)(mask + (size_t)b * Sq + c0 + tid * 4);
        __syncthreads();

        // ---- S = Q @ K^T ----
        float s[8][4];
#pragma unroll
        for (int na = 0; na < 8; ++na)
#pragma unroll
            for (int e = 0; e < 4; ++e) s[na][e] = 0.0f;

#pragma unroll
        for (int ks = 0; ks < 8; ++ks) {
            const int ka = ks * 8 + tig;
            const int kb2 = ka + 4;
            uint32_t ah[4], al[4];
            tf32_split(Qs[R * 64 + (ka ^ sw)],  ah[0], al[0]);
            tf32_split(Qs[R8 * 64 + (ka ^ sw)], ah[1], al[1]);
            tf32_split(Qs[R * 64 + (kb2 ^ sw)], ah[2], al[2]);
            tf32_split(Qs[R8 * 64 + (kb2 ^ sw)], ah[3], al[3]);
#pragma unroll
            for (int na = 0; na < 8; ++na) {
                int c = na * 8 + g;
                uint32_t bh[2];
                bh[0] = Ks[c * 64 + (ka ^ sw)];
                bh[1] = Ks[c * 64 + (kb2 ^ sw)];
                mma_tf32(s[na], ah, bh);
                mma_tf32(s[na], al, bh);
            }
        }

        // ---- mask + online softmax ----
#pragma unroll
        for (int na = 0; na < 8; ++na) {
            float m0 = msk[na * 8 + 2 * tig];
            float m1 = msk[na * 8 + 2 * tig + 1];
            s[na][0] += m0; s[na][1] += m1;
            s[na][2] += m0; s[na][3] += m1;
        }

        float mx0 = -1e30f, mx1 = -1e30f;
#pragma unroll
        for (int na = 0; na < 8; ++na) {
            mx0 = fmaxf(mx0, fmaxf(s[na][0], s[na][1]));
            mx1 = fmaxf(mx1, fmaxf(s[na][2], s[na][3]));
        }
        mx0 = fmaxf(mx0, __shfl_xor_sync(0xffffffffu, mx0, 1));
        mx0 = fmaxf(mx0, __shfl_xor_sync(0xffffffffu, mx0, 2));
        mx1 = fmaxf(mx1, __shfl_xor_sync(0xffffffffu, mx1, 1));
        mx1 = fmaxf(mx1, __shfl_xor_sync(0xffffffffu, mx1, 2));

        float mn0 = fmaxf(mrow[0], mx0);
        float mn1 = fmaxf(mrow[1], mx1);
        float fac0 = __expf(mrow[0] - mn0);
        float fac1 = __expf(mrow[1] - mn1);
        mrow[0] = mn0; mrow[1] = mn1;

        float sum0 = 0.0f, sum1 = 0.0f;
#pragma unroll
        for (int na = 0; na < 8; ++na) {
            s[na][0] = __expf(s[na][0] - mn0); sum0 += s[na][0];
            s[na][1] = __expf(s[na][1] - mn0); sum0 += s[na][1];
            s[na][2] = __expf(s[na][2] - mn1); sum1 += s[na][2];
            s[na][3] = __expf(s[na][3] - mn1); sum1 += s[na][3];
        }
        sum0 += __shfl_xor_sync(0xffffffffu, sum0, 1);
        sum0 += __shfl_xor_sync(0xffffffffu, sum0, 2);
        sum1 += __shfl_xor_sync(0xffffffffu, sum1, 1);
        sum1 += __shfl_xor_sync(0xffffffffu, sum1, 2);
        lrow[0] = lrow[0] * fac0 + sum0;
        lrow[1] = lrow[1] * fac1 + sum1;

#pragma unroll
        for (int na = 0; na < 8; ++na) {
            o[na][0] *= fac0; o[na][1] *= fac0;
            o[na][2] *= fac1; o[na][3] *= fac1;
        }

        // ---- store P (warp-private rows) ----
#pragma unroll
        for (int na = 0; na < 8; ++na) {
            int col = na * 8 + 2 * tig;
            *(float2*)&Ps[R * 64 + (col ^ sw)] = make_float2(s[na][0], s[na][1]);
            *(float2*)&Ps[R8 * 64 + (col ^ sw)] = make_float2(s[na][2], s[na][3]);
        }
        __syncwarp();

        // ---- O += P @ V ----
#pragma unroll
        for (int ks = 0; ks < 8; ++ks) {
            const int kva = ks * 8 + tig;
            const int kvb = kva + 4;
            uint32_t ph[4], pl[4];
            tf32_split(Ps[R * 64 + (kva ^ sw)],  ph[0], pl[0]);
            tf32_split(Ps[R8 * 64 + (kva ^ sw)], ph[1], pl[1]);
            tf32_split(Ps[R * 64 + (kvb ^ sw)],  ph[2], pl[2]);
            tf32_split(Ps[R8 * 64 + (kvb ^ sw)], ph[3], pl[3]);
            const int swa = tig << 3;
            const int swb = (tig + 4) << 3;
#pragma unroll
            for (int na = 0; na < 8; ++na) {
                int c = na * 8 + g;
                uint32_t vh[2];
                vh[0] = Vs[kva * 64 + (c ^ swa)];
                vh[1] = Vs[kvb * 64 + (c ^ swb)];
                mma_tf32(o[na], ph, vh);
                mma_tf32(o[na], pl, vh);
            }
        }
        __syncthreads();
    }

    // Epilogue
    float i0 = 1.0f / lrow[0];
    float i1 = 1.0f / lrow[1];
    float* Ob = O + ((size_t)(b * Sq + q0) * Hq) + ho;
#pragma unroll
    for (int na = 0; na < 8; ++na) {
        int col = na * 8 + 2 * tig;
        *(float2*)&Ob[(size_t)R * Hq + col] =
            make_float2(o[na][0] * i0, o[na][1] * i0);
        *(float2*)&Ob[(size_t)R8 * Hq + col] =
            make_float2(o[na][2] * i1, o[na][3] * i1);
    }
}

// ---------------------------------------------------------------------------
// Launch
// ---------------------------------------------------------------------------
extern "C" void kernel_launch(void* const* d_in, const int* in_sizes, int n_in,
                              void* d_out, int out_size) {
    const float* X    = (const float*)d_in[0];
    const float* mask = (const float*)d_in[1];
    const float* cs   = (const float*)d_in[2];
    const float* sn   = (const float*)d_in[3];
    const float* Wq   = (const float*)d_in[4];
    const float* Wk   = (const float*)d_in[5];
    const float* Wv   = (const float*)d_in[6];
    const float* Wo   = (const float*)d_in[7];
    float* out = (float*)d_out;

    float *Qp, *Kp, *Vp, *Ap;
    cudaGetSymbolAddress((void**)&Qp, g_Q);
    cudaGetSymbolAddress((void**)&Kp, g_K);
    cudaGetSymbolAddress((void**)&Vp, g_V);
    cudaGetSymbolAddress((void**)&Ap, g_A);

    const int M = Bq * Sq;                          // 4096
    const size_t shm_g = 4u * GP * sizeof(uint32_t);   // 32,768
    const size_t shm_a = 24640u * sizeof(uint32_t);    // 98,560

    static bool attr_set = false;
    if (!attr_set) {
        cudaFuncSetAttribute(attn_mma,
                             cudaFuncAttributeMaxDynamicSharedMemorySize,
                             (int)shm_a);
        attr_set = true;
    }

    // Pre-pass: split weights into packed bf16 hi/lo planes
    const int nw4 = Hq * Hq / 4;        // 1,048,576
    split_w_bf16<<<dim3(nw4 / 256, 4), 256>>>(
        (const float4*)Wq, (const float4*)Wk,
        (const float4*)Wv, (const float4*)Wo, nw4);

    // QKV projection (fused)
    gemm_bf3_qkv<<<dim3(48, M / 128), 256, shm_g>>>(X, Qp, Kp, Vp);

    const int PAIRS = Bq * Sq * NHq * (HDq / 2);
    rope_kernel<<<(2 * PAIRS + 255) / 256, 256>>>(Qp, Kp, cs, sn);

    attn_mma<<<dim3(Sq / 128, NHq, Bq), 256, shm_a>>>(Qp, Kp, Vp, mask, Ap);

    gemm_bf3_o<<<dim3(Hq / 128, M / 128), 256, shm_g>>>(Ap, out);
}

// round 13
// speedup vs baseline: 1.4612x; 1.0446x over previous
#include <cuda_runtime.h>
#include <cuda_bf16.h>
#include <cstddef>
#include <cstdint>

// Problem constants
#define Bq  2
#define Sq  2048
#define Hq  2048
#define NHq 32
#define HDq 64

// Scratch buffers
__device__ float    g_Q[Bq * Sq * Hq];
__device__ float    g_K[Bq * Sq * Hq];
__device__ float    g_V[Bq * Sq * Hq];
__device__ float    g_A[Bq * Sq * Hq];
// Packed bf16 hi/lo weight planes: [n][K/2] uint32 (2 bf16 per word)
__device__ uint32_t g_Wh[4][Hq * Hq / 2];
__device__ uint32_t g_Wl[4][Hq * Hq / 2];

// ---------------------------------------------------------------------------
// Helpers
// ---------------------------------------------------------------------------
// Pack two floats to bf16x2: low16 = lo_elem, high16 = hi_elem
__device__ __forceinline__ uint32_t bf16x2_pack(float hi_elem, float lo_elem) {
    uint32_t r;
    asm("cvt.rn.bf16x2.f32 %0, %1, %2;" : "=r"(r) : "f"(hi_elem), "f"(lo_elem));
    return r;
}
__device__ __forceinline__ float bfu_lo(uint32_t w) {
    return __uint_as_float(w << 16);
}
__device__ __forceinline__ float bfu_hi(uint32_t w) {
    return __uint_as_float(w & 0xFFFF0000u);
}

__device__ __forceinline__ void mma_bf16(float c[4], const uint32_t a[4],
                                         const uint32_t b[2]) {
    asm volatile(
        "mma.sync.aligned.m16n8k16.row.col.f32.bf16.bf16.f32 "
        "{%0,%1,%2,%3}, {%4,%5,%6,%7}, {%8,%9}, {%0,%1,%2,%3};\n"
        : "+f"(c[0]), "+f"(c[1]), "+f"(c[2]), "+f"(c[3])
        : "r"(a[0]), "r"(a[1]), "r"(a[2]), "r"(a[3]), "r"(b[0]), "r"(b[1]));
}

// Row-dependent column rotation for the [row][16] packed-k2 smem layout.
#define FROT(m) ((((m) >> 1) & 3) << 2)

// ---------------------------------------------------------------------------
// Pre-pass: split all four W matrices into packed bf16 hi/lo planes.
// ---------------------------------------------------------------------------
__global__ void split_w_bf16(const float4* __restrict__ w0,
                             const float4* __restrict__ w1,
                             const float4* __restrict__ w2,
                             const float4* __restrict__ w3, int n4) {
    int i = blockIdx.x * blockDim.x + threadIdx.x;
    if (i >= n4) return;
    const float4* s = (blockIdx.y == 0) ? w0 : (blockIdx.y == 1) ? w1
                      : (blockIdx.y == 2) ? w2 : w3;
    float4 v = s[i];
    uint32_t h0 = bf16x2_pack(v.y, v.x);
    uint32_t h1 = bf16x2_pack(v.w, v.z);
    float r0 = v.x - bfu_lo(h0);
    float r1 = v.y - bfu_hi(h0);
    float r2 = v.z - bfu_lo(h1);
    float r3 = v.w - bfu_hi(h1);
    uint32_t l0 = bf16x2_pack(r1, r0);
    uint32_t l1 = bf16x2_pack(r3, r2);
    ((uint2*)g_Wh[blockIdx.y])[i] = make_uint2(h0, h1);
    ((uint2*)g_Wl[blockIdx.y])[i] = make_uint2(l0, l1);
}

// ---------------------------------------------------------------------------
// bf16 3-mma GEMM (NT) — unchanged from R12 (validated WIN).
// ---------------------------------------------------------------------------
#define GP 2048   // words per plane (128*16)

__device__ __forceinline__ void gemm_bf3_core(uint32_t* sm,
        const float* __restrict__ A,
        const uint32_t* __restrict__ Wh, const uint32_t* __restrict__ Wl,
        float* __restrict__ C, int M, int N, int K, int m0, int n0) {
    uint32_t* Ah = sm;
    uint32_t* Al = sm + GP;
    uint32_t* Bh = sm + 2 * GP;
    uint32_t* Bl = sm + 3 * GP;

    const int tid  = threadIdx.x;
    const int lane = tid & 31;
    const int wid  = tid >> 5;
    const int wm   = (wid & 1) * 64;
    const int wn   = (wid >> 1) * 32;
    const int g    = lane >> 2;
    const int tig  = lane & 3;

    const int lm = tid >> 3;
    const int lk = (tid & 7) * 4;
    const int fa = FROT(lm);
    const float* Ag = A + (size_t)(m0 + lm) * K + lk;

    const int nb = tid >> 1;
    const int hb = tid & 1;
    const int fb = FROT(nb);
    const int KW = K >> 1;
    const uint32_t* Bhg = Wh + (size_t)(n0 + nb) * KW + 8 * hb;
    const uint32_t* Blg = Wl + (size_t)(n0 + nb) * KW + 8 * hb;

    float acc[4][4][4];
#pragma unroll
    for (int i = 0; i < 4; ++i)
#pragma unroll
        for (int j = 0; j < 4; ++j)
#pragma unroll
            for (int r = 0; r < 4; ++r) acc[i][j][r] = 0.0f;

    float4 pa[4];
    uint4  pwh[2], pwl[2];
#pragma unroll
    for (int it = 0; it < 4; ++it)
        pa[it] = *(const float4*)(Ag + (size_t)it * 32 * K);
#pragma unroll
    for (int v = 0; v < 2; ++v) {
        pwh[v] = *(const uint4*)(Bhg + 4 * v);
        pwl[v] = *(const uint4*)(Blg + 4 * v);
    }

    const int NCH = K >> 5;
    for (int ch = 0; ch < NCH; ++ch) {
        {
            const int k2 = lk >> 1;
            const int colA = k2 ^ fa;
#pragma unroll
            for (int it = 0; it < 4; ++it) {
                int m = lm + it * 32;
                float4 v = pa[it];
                uint32_t h0 = bf16x2_pack(v.y, v.x);
                uint32_t h1 = bf16x2_pack(v.w, v.z);
                float r0 = v.x - bfu_lo(h0);
                float r1 = v.y - bfu_hi(h0);
                float r2 = v.z - bfu_lo(h1);
                float r3 = v.w - bfu_hi(h1);
                uint32_t l0 = bf16x2_pack(r1, r0);
                uint32_t l1 = bf16x2_pack(r3, r2);
                *(uint2*)&Ah[m * 16 + colA] = make_uint2(h0, h1);
                *(uint2*)&Al[m * 16 + colA] = make_uint2(l0, l1);
            }
#pragma unroll
            for (int v = 0; v < 2; ++v) {
                int colB = (8 * hb + 4 * v) ^ fb;
                *(uint4*)&Bh[nb * 16 + colB] = pwh[v];
                *(uint4*)&Bl[nb * 16 + colB] = pwl[v];
            }
        }
        __syncthreads();

        if (ch + 1 < NCH) {
            const float* Ap = Ag + (size_t)(ch + 1) * 32;
            const uint32_t* Bhp = Bhg + (size_t)(ch + 1) * 16;
            const uint32_t* Blp = Blg + (size_t)(ch + 1) * 16;
#pragma unroll
            for (int it = 0; it < 4; ++it)
                pa[it] = *(const float4*)(Ap + (size_t)it * 32 * K);
#pragma unroll
            for (int v = 0; v < 2; ++v) {
                pwh[v] = *(const uint4*)(Bhp + 4 * v);
                pwl[v] = *(const uint4*)(Blp + 4 * v);
            }
        }

#pragma unroll
        for (int ks = 0; ks < 2; ++ks) {
            const int kc = tig + 8 * ks;

            uint32_t ah[4][4], al[4][4];
#pragma unroll
            for (int ma = 0; ma < 4; ++ma) {
                int m = wm + ma * 16 + g;
                int off = m * 16 + (kc ^ FROT(m));
                ah[ma][0] = Ah[off];
                ah[ma][1] = Ah[off + 128];
                ah[ma][2] = Ah[off ^ 4];
                ah[ma][3] = Ah[(off ^ 4) + 128];
                al[ma][0] = Al[off];
                al[ma][1] = Al[off + 128];
                al[ma][2] = Al[off ^ 4];
                al[ma][3] = Al[(off ^ 4) + 128];
            }
#pragma unroll
            for (int na = 0; na < 4; ++na) {
                int n = wn + na * 8 + g;
                int offb = n * 16 + (kc ^ FROT(n));
                uint32_t bh[2], bl[2];
                bh[0] = Bh[offb];
                bh[1] = Bh[offb ^ 4];
                bl[0] = Bl[offb];
                bl[1] = Bl[offb ^ 4];
#pragma unroll
                for (int ma = 0; ma < 4; ++ma) {
                    mma_bf16(acc[ma][na], ah[ma], bh);
                    mma_bf16(acc[ma][na], al[ma], bh);
                    mma_bf16(acc[ma][na], ah[ma], bl);
                }
            }
        }
        __syncthreads();
    }

#pragma unroll
    for (int ma = 0; ma < 4; ++ma) {
        int r0 = m0 + wm + ma * 16 + g;
#pragma unroll
        for (int na = 0; na < 4; ++na) {
            int c = n0 + wn + na * 8 + 2 * tig;
            *(float2*)&C[(size_t)r0 * N + c] =
                make_float2(acc[ma][na][0], acc[ma][na][1]);
            *(float2*)&C[(size_t)(r0 + 8) * N + c] =
                make_float2(acc[ma][na][2], acc[ma][na][3]);
        }
    }
}

__global__ void gemm_bf3_o(const float* __restrict__ A,
                           float* __restrict__ C) {
    extern __shared__ uint32_t smg[];
    gemm_bf3_core(smg, A, g_Wh[3], g_Wl[3], C, Bq * Sq, Hq, Hq,
                  blockIdx.y * 128, blockIdx.x * 128);
}

__global__ void gemm_bf3_qkv(const float* __restrict__ X,
                             float* __restrict__ Qo, float* __restrict__ Ko,
                             float* __restrict__ Vo) {
    extern __shared__ uint32_t smg[];
    const int which = blockIdx.x >> 4;
    float* C = (which == 0) ? Qo : (which == 1) ? Ko : Vo;
    gemm_bf3_core(smg, X, g_Wh[which], g_Wl[which], C, Bq * Sq, Hq, Hq,
                  blockIdx.y * 128, (blockIdx.x & 15) * 128);
}

// ---------------------------------------------------------------------------
// RoPE (in-place) on Q and K. Q also folded with 1/sqrt(HD) = 0.125.
// ---------------------------------------------------------------------------
__global__ void rope_kernel(float* __restrict__ Q, float* __restrict__ K,
                            const float* __restrict__ cs,
                            const float* __restrict__ sn) {
    const int PAIRS = Bq * Sq * NHq * (HDq / 2);
    int idx = blockIdx.x * blockDim.x + threadIdx.x;
    if (idx >= 2 * PAIRS) return;
    bool isQ = idx < PAIRS;
    int p = isQ ? idx : idx - PAIRS;

    int d = p & 31;
    int h = (p >> 5) & 31;
    int s = (p >> 10) & 2047;
    int b = p >> 21;

    size_t base = ((size_t)(b * Sq + s) * Hq) + (size_t)h * HDq + d;
    float c1 = cs[s * HDq + d],      s1 = sn[s * HDq + d];
    float c2 = cs[s * HDq + d + 32], s2 = sn[s * HDq + d + 32];

    float* T = isQ ? Q : K;
    float scale = isQ ? 0.125f : 1.0f;
    float x1 = T[base];
    float x2 = T[base + 32];
    T[base]      = (x1 * c1 - x2 * s1) * scale;
    T[base + 32] = (x2 * c2 + x1 * s2) * scale;
}

// ---------------------------------------------------------------------------
// Flash attention, bf16 3-mma everywhere.
// Q: loaded once into REGISTERS (packed bf16 hi/lo) — warp-private rows.
// K: smem [c][32w] packed along d, col = w ^ ((c&7)<<2).
// V: smem [d][32w] packed along kv (transposed at load), col = w ^ ((d&7)<<2).
// P: packed hi/lo directly in registers (a-fragment == owned s values).
// Static smem 33 KB; __launch_bounds__(256,2).
// ---------------------------------------------------------------------------
__global__ __launch_bounds__(256, 2)
void attn_bf16(const float* __restrict__ Q, const float* __restrict__ K,
               const float* __restrict__ V, const float* __restrict__ mask,
               float* __restrict__ O) {
    __shared__ uint32_t Kh[2048], Kl[2048], Vh[2048], Vl[2048];
    __shared__ float msk[64];

    const int tid  = threadIdx.x;
    const int lane = tid & 31;
    const int wid  = tid >> 5;
    const int g    = lane >> 2;
    const int tig  = lane & 3;
    const int R    = wid * 16 + g;
    const int R8   = R + 8;
    const int g4   = g << 2;

    const int b  = blockIdx.z;
    const int h  = blockIdx.y;
    const int q0 = blockIdx.x * 128;
    const size_t ho = (size_t)h * HDq;

    // ---- Load + split Q rows R, R8 into registers (packed bf16 hi/lo) ----
    uint32_t qh[2][8], ql[2][8];
    {
        const float* Qb = Q + ((size_t)(b * Sq + q0) * Hq) + ho;
#pragma unroll
        for (int rr = 0; rr < 2; ++rr) {
            const float* Qr = Qb + (size_t)(rr ? R8 : R) * Hq + 2 * tig;
#pragma unroll
            for (int u = 0; u < 8; ++u) {
                float2 q = *(const float2*)(Qr + 8 * u);
                uint32_t hw = bf16x2_pack(q.y, q.x);
                float r0 = q.x - bfu_lo(hw);
                float r1 = q.y - bfu_hi(hw);
                qh[rr][u] = hw;
                ql[rr][u] = bf16x2_pack(r1, r0);
            }
        }
    }

    float o[8][4];
#pragma unroll
    for (int na = 0; na < 8; ++na)
#pragma unroll
        for (int e = 0; e < 4; ++e) o[na][e] = 0.0f;
    float mrow[2] = {-1e30f, -1e30f};
    float lrow[2] = {0.0f, 0.0f};

    for (int t = 0; t < Sq / 64; ++t) {
        const int c0 = t * 64;
        const float* Kb = K + ((size_t)(b * Sq + c0) * Hq) + ho;
        const float* Vb = V + ((size_t)(b * Sq + c0) * Hq) + ho;

        // ---- K tile: [c][32w] packed along d ----
#pragma unroll
        for (int it = 0; it < 4; ++it) {
            int f = tid + it * 256;
            int c = f >> 4, d0 = (f & 15) << 2;
            float4 kv = *(const float4*)(Kb + (size_t)c * Hq + d0);
            uint32_t h0 = bf16x2_pack(kv.y, kv.x);
            uint32_t h1 = bf16x2_pack(kv.w, kv.z);
            float r0 = kv.x - bfu_lo(h0);
            float r1 = kv.y - bfu_hi(h0);
            float r2 = kv.z - bfu_lo(h1);
            float r3 = kv.w - bfu_hi(h1);
            int col = (d0 >> 1) ^ ((c & 7) << 2);
            *(uint2*)&Kh[c * 32 + col] = make_uint2(h0, h1);
            *(uint2*)&Kl[c * 32 + col] =
                make_uint2(bf16x2_pack(r1, r0), bf16x2_pack(r3, r2));
        }

        // ---- V tile: transposed-packed [d][32w] along kv ----
        {
            const int kv2 = lane;          // 0..31 -> rows 2kv2, 2kv2+1
            const int dbase = wid * 8;
            const float* V0 = Vb + (size_t)(2 * kv2) * Hq + dbase;
            const float* V1 = V0 + Hq;
#pragma unroll
            for (int hf = 0; hf < 2; ++hf) {
                float4 v0 = *(const float4*)(V0 + 4 * hf);
                float4 v1 = *(const float4*)(V1 + 4 * hf);
                float a0[4] = {v0.x, v0.y, v0.z, v0.w};
                float a1[4] = {v1.x, v1.y, v1.z, v1.w};
#pragma unroll
                for (int j = 0; j < 4; ++j) {
                    int d = dbase + 4 * hf + j;
                    uint32_t hv = bf16x2_pack(a1[j], a0[j]);
                    float r0 = a0[j] - bfu_lo(hv);
                    float r1 = a1[j] - bfu_hi(hv);
                    int a = d * 32 + (kv2 ^ ((d & 7) << 2));
                    Vh[a] = hv;
                    Vl[a] = bf16x2_pack(r1, r0);
                }
            }
        }
        if (tid < 16)
            *(float4*)&msk[tid * 4] =
                *(const float4*)(mask + (size_t)b * Sq + c0 + tid * 4);
        __syncthreads();

        // ---- S = Q @ K^T (bf16 3-mma, Q from registers) ----
        float s[8][4];
#pragma unroll
        for (int na = 0; na < 8; ++na)
#pragma unroll
            for (int e = 0; e < 4; ++e) s[na][e] = 0.0f;

#pragma unroll
        for (int ks = 0; ks < 4; ++ks) {
            uint32_t ah[4] = {qh[0][2 * ks], qh[1][2 * ks],
                              qh[0][2 * ks + 1], qh[1][2 * ks + 1]};
            uint32_t al[4] = {ql[0][2 * ks], ql[1][2 * ks],
                              ql[0][2 * ks + 1], ql[1][2 * ks + 1]};
            const int wq = (8 * ks + tig) ^ g4;
#pragma unroll
            for (int na = 0; na < 8; ++na) {
                int cb = (na * 8 + g) * 32;
                uint32_t bh[2] = {Kh[cb + wq], Kh[cb + (wq ^ 4)]};
                uint32_t bl[2] = {Kl[cb + wq], Kl[cb + (wq ^ 4)]};
                mma_bf16(s[na], ah, bh);
                mma_bf16(s[na], al, bh);
                mma_bf16(s[na], ah, bl);
            }
        }

        // ---- mask + online softmax ----
#pragma unroll
        for (int na = 0; na < 8; ++na) {
            float m0 = msk[na * 8 + 2 * tig];
            float m1 = msk[na * 8 + 2 * tig + 1];
            s[na][0] += m0; s[na][1] += m1;
            s[na][2] += m0; s[na][3] += m1;
        }

        float mx0 = -1e30f, mx1 = -1e30f;
#pragma unroll
        for (int na = 0; na < 8; ++na) {
            mx0 = fmaxf(mx0, fmaxf(s[na][0], s[na][1]));
            mx1 = fmaxf(mx1, fmaxf(s[na][2], s[na][3]));
        }
        mx0 = fmaxf(mx0, __shfl_xor_sync(0xffffffffu, mx0, 1));
        mx0 = fmaxf(mx0, __shfl_xor_sync(0xffffffffu, mx0, 2));
        mx1 = fmaxf(mx1, __shfl_xor_sync(0xffffffffu, mx1, 1));
        mx1 = fmaxf(mx1, __shfl_xor_sync(0xffffffffu, mx1, 2));

        float mn0 = fmaxf(mrow[0], mx0);
        float mn1 = fmaxf(mrow[1], mx1);
        float fac0 = __expf(mrow[0] - mn0);
        float fac1 = __expf(mrow[1] - mn1);
        mrow[0] = mn0; mrow[1] = mn1;

        float sum0 = 0.0f, sum1 = 0.0f;
#pragma unroll
        for (int na = 0; na < 8; ++na) {
            s[na][0] = __expf(s[na][0] - mn0); sum0 += s[na][0];
            s[na][1] = __expf(s[na][1] - mn0); sum0 += s[na][1];
            s[na][2] = __expf(s[na][2] - mn1); sum1 += s[na][2];
            s[na][3] = __expf(s[na][3] - mn1); sum1 += s[na][3];
        }
        sum0 += __shfl_xor_sync(0xffffffffu, sum0, 1);
        sum0 += __shfl_xor_sync(0xffffffffu, sum0, 2);
        sum1 += __shfl_xor_sync(0xffffffffu, sum1, 1);
        sum1 += __shfl_xor_sync(0xffffffffu, sum1, 2);
        lrow[0] = lrow[0] * fac0 + sum0;
        lrow[1] = lrow[1] * fac1 + sum1;

#pragma unroll
        for (int na = 0; na < 8; ++na) {
            o[na][0] *= fac0; o[na][1] *= fac0;
            o[na][2] *= fac1; o[na][3] *= fac1;
        }

        // ---- pack P into registers (hi + residual), no smem ----
        uint32_t ph[2][8], pl[2][8];
#pragma unroll
        for (int na = 0; na < 8; ++na) {
            uint32_t h0 = bf16x2_pack(s[na][1], s[na][0]);
            float r0 = s[na][0] - bfu_lo(h0);
            float r1 = s[na][1] - bfu_hi(h0);
            ph[0][na] = h0;
            pl[0][na] = bf16x2_pack(r1, r0);
            uint32_t h1 = bf16x2_pack(s[na][3], s[na][2]);
            float r2 = s[na][2] - bfu_lo(h1);
            float r3 = s[na][3] - bfu_hi(h1);
            ph[1][na] = h1;
            pl[1][na] = bf16x2_pack(r3, r2);
        }

        // ---- O += P @ V (bf16 3-mma, P from registers) ----
#pragma unroll
        for (int ks = 0; ks < 4; ++ks) {
            uint32_t ah[4] = {ph[0][2 * ks], ph[1][2 * ks],
                              ph[0][2 * ks + 1], ph[1][2 * ks + 1]};
            uint32_t al[4] = {pl[0][2 * ks], pl[1][2 * ks],
                              pl[0][2 * ks + 1], pl[1][2 * ks + 1]};
            const int wv = (8 * ks + tig) ^ g4;
#pragma unroll
            for (int na = 0; na < 8; ++na) {
                int db = (na * 8 + g) * 32;
                uint32_t vh[2] = {Vh[db + wv], Vh[db + (wv ^ 4)]};
                uint32_t vl[2] = {Vl[db + wv], Vl[db + (wv ^ 4)]};
                mma_bf16(o[na], ah, vh);
                mma_bf16(o[na], al, vh);
                mma_bf16(o[na], ah, vl);
            }
        }
        __syncthreads();
    }

    // Epilogue
    float i0 = 1.0f / lrow[0];
    float i1 = 1.0f / lrow[1];
    float* Ob = O + ((size_t)(b * Sq + q0) * Hq) + ho;
#pragma unroll
    for (int na = 0; na < 8; ++na) {
        int col = na * 8 + 2 * tig;
        *(float2*)&Ob[(size_t)R * Hq + col] =
            make_float2(o[na][0] * i0, o[na][1] * i0);
        *(float2*)&Ob[(size_t)R8 * Hq + col] =
            make_float2(o[na][2] * i1, o[na][3] * i1);
    }
}

// ---------------------------------------------------------------------------
// Launch
// ---------------------------------------------------------------------------
extern "C" void kernel_launch(void* const* d_in, const int* in_sizes, int n_in,
                              void* d_out, int out_size) {
    const float* X    = (const float*)d_in[0];
    const float* mask = (const float*)d_in[1];
    const float* cs   = (const float*)d_in[2];
    const float* sn   = (const float*)d_in[3];
    float* out = (float*)d_out;

    float *Qp, *Kp, *Vp, *Ap;
    cudaGetSymbolAddress((void**)&Qp, g_Q);
    cudaGetSymbolAddress((void**)&Kp, g_K);
    cudaGetSymbolAddress((void**)&Vp, g_V);
    cudaGetSymbolAddress((void**)&Ap, g_A);

    const int M = Bq * Sq;                             // 4096
    const size_t shm_g = 4u * GP * sizeof(uint32_t);   // 32,768

    // Pre-pass: split weights into packed bf16 hi/lo planes
    const int nw4 = Hq * Hq / 4;
    split_w_bf16<<<dim3(nw4 / 256, 4), 256>>>(
        (const float4*)d_in[4], (const float4*)d_in[5],
        (const float4*)d_in[6], (const float4*)d_in[7], nw4);

    // QKV projection (fused)
    gemm_bf3_qkv<<<dim3(48, M / 128), 256, shm_g>>>(X, Qp, Kp, Vp);

    const int PAIRS = Bq * Sq * NHq * (HDq / 2);
    rope_kernel<<<(2 * PAIRS + 255) / 256, 256>>>(Qp, Kp, cs, sn);

    attn_bf16<<<dim3(Sq / 128, NHq, Bq), 256>>>(Qp, Kp, Vp, mask, Ap);

    gemm_bf3_o<<<dim3(Hq / 128, M / 128), 256, shm_g>>>(Ap, out);
}